// round 1
// baseline (speedup 1.0000x reference)
#include <cuda_runtime.h>
#include <math.h>

#define N_ATOMS 10000
#define N_PAIRS 100000
#define H 64
#define R 32
#define MAX_Z 100

// ---------------- scratch (static device globals; no allocation) ----------------
__device__ float g_U[MAX_Z * H];          // emb @ W1.T + b
__device__ float g_V[MAX_Z * H];          // emb @ W2.T
__device__ int   g_counts[N_ATOMS];
__device__ int   g_offsets[N_ATOMS + 1];
__device__ int   g_cursor[N_ATOMS];
__device__ int   g_sorted[N_PAIRS];
__device__ float g_comp[10][N_ATOMS * H]; // cI, wx,wy,wz, sxx,syy,szz,sxy,sxz,syz
__device__ float g_tnorm[N_ATOMS * H];    // layernormed tensor norm
__device__ float g_mlp[N_ATOMS * 3 * H];  // MLP output (N,192)

// rbf constants
#define RBF_START 0.60653065971263342f   // exp(-0.5)
#define RBF_ALPHA 10.0f

// ---------------- K1: per-element-type embedding transform ----------------
__global__ void k_uv(const float* __restrict__ emb, const float* __restrict__ w2,
                     const float* __restrict__ b2) {
    __shared__ float se[H];
    int t = blockIdx.x;          // element type
    int h = threadIdx.x;         // output channel
    se[h] = emb[t * H + h];
    __syncthreads();
    float u = b2[h];
    float v = 0.0f;
    const float* wr = w2 + h * 2 * H;
#pragma unroll
    for (int k = 0; k < H; k++) {
        u += se[k] * wr[k];
        v += se[k] * wr[H + k];
    }
    g_U[t * H + h] = u;
    g_V[t * H + h] = v;
}

// ---------------- sort pairs by src (counting sort) ----------------
__global__ void k_zero() {
    int i = blockIdx.x * blockDim.x + threadIdx.x;
    if (i < N_ATOMS) g_counts[i] = 0;
}

__global__ void k_hist(const int* __restrict__ src) {
    int i = blockIdx.x * blockDim.x + threadIdx.x;
    if (i < N_PAIRS) atomicAdd(&g_counts[src[i]], 1);
}

__global__ void k_scan() {
    __shared__ int part[1024];
    int t = threadIdx.x;
    int base = t * 10;
    int local[10];
    int s = 0;
#pragma unroll
    for (int i = 0; i < 10; i++) {
        int idx = base + i;
        int c = (idx < N_ATOMS) ? g_counts[idx] : 0;
        local[i] = s;
        s += c;
    }
    part[t] = s;
    __syncthreads();
    for (int off = 1; off < 1024; off <<= 1) {
        int v = (t >= off) ? part[t - off] : 0;
        __syncthreads();
        part[t] += v;
        __syncthreads();
    }
    int excl = part[t] - s;
#pragma unroll
    for (int i = 0; i < 10; i++) {
        int idx = base + i;
        if (idx < N_ATOMS) {
            int o = excl + local[i];
            g_offsets[idx] = o;
            g_cursor[idx]  = o;
        }
    }
    if (t == 1023) g_offsets[N_ATOMS] = part[1023];
}

__global__ void k_scatter(const int* __restrict__ src) {
    int i = blockIdx.x * blockDim.x + threadIdx.x;
    if (i < N_PAIRS) {
        int pos = atomicAdd(&g_cursor[src[i]], 1);
        g_sorted[pos] = i;
    }
}

// ---------------- K_pairs: per-pair features + segment sum + layernorm ----------------
// one warp per atom; 8 atoms per 256-thread block. lane owns h0=2*lane, h1=2*lane+1.
__global__ void __launch_bounds__(256) k_pairs(
    const int* __restrict__ anum, const int* __restrict__ pdst,
    const float* __restrict__ dij, const float* __restrict__ rij,
    const float* __restrict__ dp1w, const float* __restrict__ dp1b,
    const float* __restrict__ dp2w, const float* __restrict__ dp2b,
    const float* __restrict__ dp3w, const float* __restrict__ dp3b,
    const float* __restrict__ lng, const float* __restrict__ lnb) {
    __shared__ __align__(16) float sh_dp[3][R * 66];   // [comp][r*66 + h], stride 66 avoids STS/LDS conflicts
    __shared__ float sh_rbf[8][32];

    // stage dp weights: global [h][r] -> shared [r][h]
    for (int e = threadIdx.x; e < 3 * R * H; e += 256) {
        int c   = e >> 11;       // /2048
        int rem = e & 2047;      // h*32 + r
        int h   = rem >> 5;
        int r   = rem & 31;
        const float* s = (c == 0) ? dp1w : ((c == 1) ? dp2w : dp3w);
        sh_dp[c][r * 66 + h] = s[rem];
    }
    __syncthreads();

    int w    = threadIdx.x >> 5;
    int lane = threadIdx.x & 31;
    int a    = blockIdx.x * 8 + w;   // grid = 1250 => exactly N_ATOMS

    int start = g_offsets[a];
    int end   = g_offsets[a + 1];
    int za    = anum[a];

    const float2* U2 = reinterpret_cast<const float2*>(g_U);
    const float2* V2 = reinterpret_cast<const float2*>(g_V);
    float2 ub = U2[za * 32 + lane];
    float2 b1 = reinterpret_cast<const float2*>(dp1b)[lane];
    float2 b2 = reinterpret_cast<const float2*>(dp2b)[lane];
    float2 b3 = reinterpret_cast<const float2*>(dp3b)[lane];

    const float rbf_step = (1.0f - RBF_START) * (1.0f / 31.0f);
    float tb = (1.0f - RBF_START) * (2.0f / 32.0f);
    const float beta = 1.0f / (tb * tb);
    const float mlane = RBF_START + rbf_step * (float)lane;

    float cI0=0,wx0=0,wy0=0,wz0=0,sxx0=0,syy0=0,szz0=0,sxy0=0,sxz0=0,syz0=0;
    float cI1=0,wx1=0,wy1=0,wz1=0,sxx1=0,syy1=0,szz1=0,sxy1=0,sxz1=0,syz1=0;

    for (int it = start; it < end; ++it) {
        int p   = g_sorted[it];
        float d = dij[p];
        if (d >= 0.5f) continue;                 // cutoff zero -> zero contribution (warp-uniform)
        float rc = 0.5f * (cospif(2.0f * d) + 1.0f);

        int zd = anum[pdst[p]];
        float2 vb = V2[zd * 32 + lane];

        float rx = rij[3 * p], ry = rij[3 * p + 1], rz = rij[3 * p + 2];
        float inv = 1.0f / d;
        float ux = rx * inv, uy = ry * inv, uz = rz * inv;
        float tr3 = (ux * ux + uy * uy + uz * uz) * (1.0f / 3.0f);
        float txx = ux * ux - tr3, tyy = uy * uy - tr3, tzz = uz * uz - tr3;
        float txy = ux * uy, txz = ux * uz, tyz = uy * uz;

        float ee  = expf(-RBF_ALPHA * d);
        float dfm = ee - mlane;
        float rb  = expf(-beta * dfm * dfm) * rc;
        __syncwarp();
        sh_rbf[w][lane] = rb;
        __syncwarp();

        float g1a=0,g1b=0,g2a=0,g2b=0,g3a=0,g3b=0;
#pragma unroll
        for (int r = 0; r < R; r++) {
            float v = sh_rbf[w][r];
            float2 w1 = *reinterpret_cast<const float2*>(&sh_dp[0][r * 66 + 2 * lane]);
            float2 w2 = *reinterpret_cast<const float2*>(&sh_dp[1][r * 66 + 2 * lane]);
            float2 w3 = *reinterpret_cast<const float2*>(&sh_dp[2][r * 66 + 2 * lane]);
            g1a += v * w1.x; g1b += v * w1.y;
            g2a += v * w2.x; g2b += v * w2.y;
            g3a += v * w3.x; g3b += v * w3.y;
        }

        float C0 = rc * (ub.x + vb.x);
        float C1 = rc * (ub.y + vb.y);
        float f10 = (g1a + b1.x) * C0,            f11 = (g1b + b1.y) * C1;
        float f20 = (g2a + b2.x) * C0 * 10.0f,    f21 = (g2b + b2.y) * C1 * 10.0f;
        float f30 = (g3a + b3.x) * C0 * 100.0f,   f31 = (g3b + b3.y) * C1 * 100.0f;

        cI0 += f10;            cI1 += f11;
        wx0 += f20 * ux;       wx1 += f21 * ux;
        wy0 += f20 * uy;       wy1 += f21 * uy;
        wz0 += f20 * uz;       wz1 += f21 * uz;
        sxx0 += f30 * txx;     sxx1 += f31 * txx;
        syy0 += f30 * tyy;     syy1 += f31 * tyy;
        szz0 += f30 * tzz;     szz1 += f31 * tzz;
        sxy0 += f30 * txy;     sxy1 += f31 * txy;
        sxz0 += f30 * txz;     sxz1 += f31 * txz;
        syz0 += f30 * tyz;     syz1 += f31 * tyz;
    }

    // tensor frobenius norm^2 per h
    float tA0 = cI0 + sxx0, tB0 = cI0 + syy0, tC0 = cI0 + szz0;
    float tn0 = tA0*tA0 + tB0*tB0 + tC0*tC0
              + 2.0f * (sxy0*sxy0 + wz0*wz0 + sxz0*sxz0 + wy0*wy0 + syz0*syz0 + wx0*wx0);
    float tA1 = cI1 + sxx1, tB1 = cI1 + syy1, tC1 = cI1 + szz1;
    float tn1 = tA1*tA1 + tB1*tB1 + tC1*tC1
              + 2.0f * (sxy1*sxy1 + wz1*wz1 + sxz1*sxz1 + wy1*wy1 + syz1*syz1 + wx1*wx1);

    // layernorm over H (warp reduce; 2 vals/lane)
    float ssum = tn0 + tn1;
#pragma unroll
    for (int o = 16; o; o >>= 1) ssum += __shfl_xor_sync(0xffffffffu, ssum, o);
    float mu = ssum * (1.0f / 64.0f);
    float e0 = tn0 - mu, e1 = tn1 - mu;
    float vsum = e0 * e0 + e1 * e1;
#pragma unroll
    for (int o = 16; o; o >>= 1) vsum += __shfl_xor_sync(0xffffffffu, vsum, o);
    float rstd = rsqrtf(vsum * (1.0f / 64.0f) + 1e-5f);

    float2 lg = reinterpret_cast<const float2*>(lng)[lane];
    float2 lb = reinterpret_cast<const float2*>(lnb)[lane];
    float2 nrm;
    nrm.x = e0 * rstd * lg.x + lb.x;
    nrm.y = e1 * rstd * lg.y + lb.y;
    reinterpret_cast<float2*>(g_tnorm)[a * 32 + lane] = nrm;

    int oidx = a * 32 + lane;
    reinterpret_cast<float2*>(g_comp[0])[oidx] = make_float2(cI0, cI1);
    reinterpret_cast<float2*>(g_comp[1])[oidx] = make_float2(wx0, wx1);
    reinterpret_cast<float2*>(g_comp[2])[oidx] = make_float2(wy0, wy1);
    reinterpret_cast<float2*>(g_comp[3])[oidx] = make_float2(wz0, wz1);
    reinterpret_cast<float2*>(g_comp[4])[oidx] = make_float2(sxx0, sxx1);
    reinterpret_cast<float2*>(g_comp[5])[oidx] = make_float2(syy0, syy1);
    reinterpret_cast<float2*>(g_comp[6])[oidx] = make_float2(szz0, szz1);
    reinterpret_cast<float2*>(g_comp[7])[oidx] = make_float2(sxy0, sxy1);
    reinterpret_cast<float2*>(g_comp[8])[oidx] = make_float2(sxz0, sxz1);
    reinterpret_cast<float2*>(g_comp[9])[oidx] = make_float2(syz0, syz1);
}

// ---------------- K_mlp: norm -> silu(ls1) -> silu(ls2) ----------------
// 16 atoms per block, 192 threads, weights staged in shared.
__global__ void __launch_bounds__(192) k_mlp(
    const float* __restrict__ ls1w, const float* __restrict__ ls1b,
    const float* __restrict__ ls2w, const float* __restrict__ ls2b) {
    extern __shared__ float sm[];
    float* w1   = sm;                  // [k*128+j]  64x128
    float* w2   = w1 + 64 * 128;       // [k*192+j] 128x192
    float* b1s  = w2 + 128 * 192;      // 128
    float* b2s  = b1s + 128;           // 192
    float* nsh  = b2s + 192;           // 16x64
    float* h1sh = nsh + 16 * 64;       // 16x128

    int tid = threadIdx.x;
    int ab  = blockIdx.x * 16;

    for (int e = tid; e < 64 * 128; e += 192) {       // ls1_w [j][k] -> w1[k][j]
        int j = e >> 6, k = e & 63;
        w1[k * 128 + j] = ls1w[e];
    }
    for (int e = tid; e < 128 * 192; e += 192) {      // ls2_w [j][k] -> w2[k][j]
        int j = e >> 7, k = e & 127;
        w2[k * 192 + j] = ls2w[e];
    }
    if (tid < 128) b1s[tid] = ls1b[tid];
    b2s[tid] = ls2b[tid];
    for (int e = tid; e < 16 * 64; e += 192) nsh[e] = g_tnorm[ab * 64 + e];
    __syncthreads();

    for (int e = tid; e < 16 * 128; e += 192) {
        int aa = e >> 7, j = e & 127;
        float acc = b1s[j];
        const float* nr = nsh + aa * 64;
#pragma unroll 8
        for (int k = 0; k < 64; k++) acc += nr[k] * w1[k * 128 + j];
        h1sh[aa * 128 + j] = acc / (1.0f + expf(-acc));
    }
    __syncthreads();

#pragma unroll 1
    for (int aa = 0; aa < 16; aa++) {
        int j = tid;  // exactly 192
        float acc = b2s[j];
        const float* hr = h1sh + aa * 128;
#pragma unroll 8
        for (int k = 0; k < 128; k++) acc += hr[k] * w2[k * 192 + j];
        g_mlp[(ab + aa) * 192 + j] = acc / (1.0f + expf(-acc));
    }
}

// ---------------- K_final: 10 channel-mix GEMMs + 3x3 assembly ----------------
// 16 atoms per block, 640 threads = (comp c in 0..9) x (g in 0..63)
__global__ void __launch_bounds__(640) k_final(
    const float* __restrict__ lt0, const float* __restrict__ lt1,
    const float* __restrict__ lt2, float* __restrict__ out) {
    extern __shared__ float sm[];
    float* lt  = sm;                  // [m][h*64+g]  3x4096
    float* csh = lt + 3 * 4096;       // [(a*10+c)*64+h] 10240
    float* res = csh + 10240;         // [c*64+g] 640
    float* nm  = res + 640;           // [a*192+j] 3072

    int tid = threadIdx.x;
    int ab  = blockIdx.x * 16;

    for (int e = tid; e < 4096; e += 640) {           // ltX [g][h] -> lt[m][h][g]
        int g = e >> 6, h = e & 63;
        lt[h * 64 + g]            = lt0[e];
        lt[4096 + h * 64 + g]     = lt1[e];
        lt[2 * 4096 + h * 64 + g] = lt2[e];
    }
    for (int e = tid; e < 10240; e += 640) {          // comps: [a][c][h]
        int aa = e / 640, rem = e - aa * 640;         // rem = c*64+h
        int c = rem >> 6, h = rem & 63;
        csh[e] = g_comp[c][(ab + aa) * 64 + h];
    }
    for (int e = tid; e < 3072; e += 640) nm[e] = g_mlp[ab * 192 + e];
    __syncthreads();

    int c = tid >> 6;
    int g = tid & 63;
    int m = (c == 0) ? 0 : ((c < 4) ? 1 : 2);
    const float* wrow = lt + m * 4096;

    float acc[16];
#pragma unroll
    for (int aa = 0; aa < 16; aa++) acc[aa] = 0.0f;

#pragma unroll 4
    for (int h = 0; h < 64; h++) {
        float wv = wrow[h * 64 + g];
        const float* cb = csh + c * 64 + h;
#pragma unroll
        for (int aa = 0; aa < 16; aa++) acc[aa] += wv * cb[aa * 640];
    }

#pragma unroll 1
    for (int aa = 0; aa < 16; aa++) {
        __syncthreads();
        res[c * 64 + g] = acc[aa];
        __syncthreads();
        if (tid < 576) {
            int g2 = tid / 9;
            int ij = tid - g2 * 9;
            float n0 = nm[aa * 192 + g2 * 3 + 0];
            float n1 = nm[aa * 192 + g2 * 3 + 1];
            float n2 = nm[aa * 192 + g2 * 3 + 2];
            float cIv = res[g2];
            float wx = res[64 + g2],  wy = res[128 + g2], wz = res[192 + g2];
            float sxx = res[256 + g2], syy = res[320 + g2], szz = res[384 + g2];
            float sxy = res[448 + g2], sxz = res[512 + g2], syz = res[576 + g2];
            float ival = 0.0f, aval = 0.0f, sval = 0.0f;
            switch (ij) {
                case 0: ival = cIv; sval = sxx; break;
                case 1: aval = -wz; sval = sxy; break;
                case 2: aval =  wy; sval = sxz; break;
                case 3: aval =  wz; sval = sxy; break;
                case 4: ival = cIv; sval = syy; break;
                case 5: aval = -wx; sval = syz; break;
                case 6: aval = -wy; sval = sxz; break;
                case 7: aval =  wx; sval = syz; break;
                case 8: ival = cIv; sval = szz; break;
            }
            out[((ab + aa) * 64 + g2) * 9 + ij] = ival * n0 + aval * n1 + sval * n2;
        }
    }
}

// ---------------- launch ----------------
extern "C" void kernel_launch(void* const* d_in, const int* in_sizes, int n_in,
                              void* d_out, int out_size) {
    const int*   anum  = (const int*)d_in[0];
    const int*   psrc  = (const int*)d_in[1];
    const int*   pdst  = psrc + N_PAIRS;
    const float* dij   = (const float*)d_in[2];
    const float* rij   = (const float*)d_in[3];
    const float* emb   = (const float*)d_in[4];
    const float* e2w   = (const float*)d_in[5];
    const float* e2b   = (const float*)d_in[6];
    const float* dp1w  = (const float*)d_in[7];
    const float* dp1b  = (const float*)d_in[8];
    const float* dp2w  = (const float*)d_in[9];
    const float* dp2b  = (const float*)d_in[10];
    const float* dp3w  = (const float*)d_in[11];
    const float* dp3b  = (const float*)d_in[12];
    const float* lt0   = (const float*)d_in[13];
    const float* lt1   = (const float*)d_in[14];
    const float* lt2   = (const float*)d_in[15];
    const float* ls1w  = (const float*)d_in[16];
    const float* ls1b  = (const float*)d_in[17];
    const float* ls2w  = (const float*)d_in[18];
    const float* ls2b  = (const float*)d_in[19];
    const float* lng   = (const float*)d_in[20];
    const float* lnb   = (const float*)d_in[21];
    float* out = (float*)d_out;

    const size_t mlp_smem   = (64*128 + 128*192 + 128 + 192 + 16*64 + 16*128) * sizeof(float);
    const size_t final_smem = (3*4096 + 10240 + 640 + 3072) * sizeof(float);
    cudaFuncSetAttribute(k_mlp,   cudaFuncAttributeMaxDynamicSharedMemorySize, (int)mlp_smem);
    cudaFuncSetAttribute(k_final, cudaFuncAttributeMaxDynamicSharedMemorySize, (int)final_smem);

    k_uv<<<MAX_Z, H>>>(emb, e2w, e2b);
    k_zero<<<(N_ATOMS + 255) / 256, 256>>>();
    k_hist<<<(N_PAIRS + 255) / 256, 256>>>(psrc);
    k_scan<<<1, 1024>>>();
    k_scatter<<<(N_PAIRS + 255) / 256, 256>>>(psrc);
    k_pairs<<<N_ATOMS / 8, 256>>>(anum, pdst, dij, rij,
                                  dp1w, dp1b, dp2w, dp2b, dp3w, dp3b, lng, lnb);
    k_mlp<<<N_ATOMS / 16, 192, mlp_smem>>>(ls1w, ls1b, ls2w, ls2b);
    k_final<<<N_ATOMS / 16, 640, final_smem>>>(lt0, lt1, lt2, out);
}

// round 3
// speedup vs baseline: 1.7501x; 1.7501x over previous
#include <cuda_runtime.h>
#include <math.h>

#define N_ATOMS 10000
#define N_PAIRS 100000
#define H 64
#define R 32
#define MAX_Z 100

typedef unsigned long long ull;

// -------- f32x2 packed math helpers (sm_10x) --------
__device__ __forceinline__ ull pk2(float x, float y) {
    ull r; asm("mov.b64 %0,{%1,%2};" : "=l"(r) : "f"(x), "f"(y)); return r;
}
__device__ __forceinline__ float2 up2(ull v) {
    float2 f; asm("mov.b64 {%0,%1},%2;" : "=f"(f.x), "=f"(f.y) : "l"(v)); return f;
}
__device__ __forceinline__ ull dup2(float x) { return pk2(x, x); }
__device__ __forceinline__ ull fma2_(ull a, ull b, ull c) {
    ull d; asm("fma.rn.f32x2 %0,%1,%2,%3;" : "=l"(d) : "l"(a), "l"(b), "l"(c)); return d;
}
__device__ __forceinline__ ull add2_(ull a, ull b) {
    ull d; asm("add.rn.f32x2 %0,%1,%2;" : "=l"(d) : "l"(a), "l"(b)); return d;
}
__device__ __forceinline__ ull mul2_(ull a, ull b) {
    ull d; asm("mul.rn.f32x2 %0,%1,%2;" : "=l"(d) : "l"(a), "l"(b)); return d;
}

// ---------------- scratch ----------------
__device__ __align__(16) float g_U[MAX_Z * H];
__device__ __align__(16) float g_V[MAX_Z * H];
__device__ int   g_counts[N_ATOMS];
__device__ int   g_offsets[N_ATOMS + 1];
__device__ int   g_cursor[N_ATOMS];
__device__ int   g_sorted[N_PAIRS];
__device__ __align__(16) float g_comp[10][N_ATOMS * H];
__device__ __align__(16) float g_tnorm[N_ATOMS * H];
__device__ __align__(16) float g_mlp[N_ATOMS * 3 * H];

#define RBF_START 0.60653065971263342f
#define RBF_ALPHA 10.0f

// ---------------- K1: embedding transform ----------------
__global__ void k_uv(const float* __restrict__ emb, const float* __restrict__ w2,
                     const float* __restrict__ b2) {
    __shared__ float se[H];
    int t = blockIdx.x;
    int h = threadIdx.x;
    se[h] = emb[t * H + h];
    __syncthreads();
    float u = b2[h];
    float v = 0.0f;
    const float* wr = w2 + h * 2 * H;
#pragma unroll
    for (int k = 0; k < H; k++) {
        u += se[k] * wr[k];
        v += se[k] * wr[H + k];
    }
    g_U[t * H + h] = u;
    g_V[t * H + h] = v;
}

// ---------------- counting sort ----------------
__global__ void k_zero() {
    int i = blockIdx.x * blockDim.x + threadIdx.x;
    if (i < N_ATOMS) g_counts[i] = 0;
}

__global__ void k_hist(const int* __restrict__ src) {
    int i = blockIdx.x * blockDim.x + threadIdx.x;
    if (i < N_PAIRS) atomicAdd(&g_counts[src[i]], 1);
}

__global__ void k_scan() {
    __shared__ int wsum[32];
    int t = threadIdx.x;
    int lane = t & 31, wid = t >> 5;
    int base = t * 10;
    int loc[10];
    int s = 0;
#pragma unroll
    for (int i = 0; i < 10; i++) {
        int idx = base + i;
        int c = (idx < N_ATOMS) ? g_counts[idx] : 0;
        loc[i] = s;
        s += c;
    }
    int v = s;
#pragma unroll
    for (int o = 1; o < 32; o <<= 1) {
        int u = __shfl_up_sync(0xffffffffu, v, o);
        if (lane >= o) v += u;
    }
    if (lane == 31) wsum[wid] = v;
    __syncthreads();
    if (wid == 0) {
        int x = wsum[lane];
#pragma unroll
        for (int o = 1; o < 32; o <<= 1) {
            int u = __shfl_up_sync(0xffffffffu, x, o);
            if (lane >= o) x += u;
        }
        wsum[lane] = x;
    }
    __syncthreads();
    int wbase = (wid > 0) ? wsum[wid - 1] : 0;
    int excl = wbase + v - s;
#pragma unroll
    for (int i = 0; i < 10; i++) {
        int idx = base + i;
        if (idx < N_ATOMS) {
            int o = excl + loc[i];
            g_offsets[idx] = o;
            g_cursor[idx]  = o;
        }
    }
    if (t == 1023) g_offsets[N_ATOMS] = wbase + v;
}

__global__ void k_scatter(const int* __restrict__ src) {
    int i = blockIdx.x * blockDim.x + threadIdx.x;
    if (i < N_PAIRS) {
        int pos = atomicAdd(&g_cursor[src[i]], 1);
        g_sorted[pos] = i;
    }
}

// ---------------- K_pairs ----------------
// warp per atom; lane owns h = 2*lane, 2*lane+1. Pairs batched 4-wide so
// weight LDS traffic is amortized; all inner FMAs are packed f32x2.
__global__ void __launch_bounds__(256) k_pairs(
    const int* __restrict__ anum, const int* __restrict__ pdst,
    const float* __restrict__ dij, const float* __restrict__ rij,
    const float* __restrict__ dp1w, const float* __restrict__ dp2w,
    const float* __restrict__ dp3w,
    const float* __restrict__ dp1b, const float* __restrict__ dp2b,
    const float* __restrict__ dp3b,
    const float* __restrict__ lng, const float* __restrict__ lnb) {
    __shared__ __align__(16) float4 sh_dpA[R * 32];   // [r*32+lane] = (w1_h0,w1_h1,w2_h0,w2_h1)
    __shared__ __align__(16) float2 sh_dpB[R * 32];   // (w3_h0,w3_h1)
    __shared__ __align__(16) float4 sh_rbf[8][R];     // [warp][r] = rb of 4 batched pairs

    for (int e = threadIdx.x; e < R * 32; e += 256) {
        int r = e >> 5, l = e & 31;
        int h0 = 2 * l, h1 = 2 * l + 1;
        sh_dpA[e] = make_float4(dp1w[h0 * R + r], dp1w[h1 * R + r],
                                dp2w[h0 * R + r], dp2w[h1 * R + r]);
        sh_dpB[e] = make_float2(dp3w[h0 * R + r], dp3w[h1 * R + r]);
    }
    __syncthreads();

    int w    = threadIdx.x >> 5;
    int lane = threadIdx.x & 31;
    int a    = blockIdx.x * 8 + w;

    int start = g_offsets[a];
    int end   = g_offsets[a + 1];
    int za    = anum[a];

    const float2* U2 = reinterpret_cast<const float2*>(g_U);
    const float2* V2 = reinterpret_cast<const float2*>(g_V);
    float2 ubv = U2[za * 32 + lane];
    float2 b1v = reinterpret_cast<const float2*>(dp1b)[lane];
    float2 b2v = reinterpret_cast<const float2*>(dp2b)[lane];
    float2 b3v = reinterpret_cast<const float2*>(dp3b)[lane];
    ull b1p = pk2(b1v.x, b1v.y);
    ull b2p = pk2(b2v.x, b2v.y);
    ull b3p = pk2(b3v.x, b3v.y);
    const ull tenp = dup2(10.0f);
    const ull hunp = dup2(100.0f);

    const float rbf_step = (1.0f - RBF_START) * (1.0f / 31.0f);
    float tb = (1.0f - RBF_START) * (2.0f / 32.0f);
    const float beta = 1.0f / (tb * tb);
    const float mlane = RBF_START + rbf_step * (float)lane;

    ull cI = 0, wx = 0, wy = 0, wz = 0;
    ull sxx = 0, syy = 0, szz = 0, sxy = 0, sxz = 0, syz = 0;

    float* rbf_w = reinterpret_cast<float*>(sh_rbf[w]);

    for (int it = start; it < end; it += 4) {
        float C0[4], C1[4];
        float uxA[4], uyA[4], uzA[4];
        float txxA[4], tyyA[4], tzzA[4], txyA[4], txzA[4], tyzA[4];

#pragma unroll
        for (int pi = 0; pi < 4; pi++) {
            int idx = it + pi;
            bool valid = idx < end;
            int p = g_sorted[valid ? idx : start];
            float d = dij[p];
            float rc = (valid && d < 0.5f)
                       ? 0.5f * (__cosf(6.2831853071795865f * d) + 1.0f) : 0.0f;
            int zd = anum[pdst[p]];
            float2 vb = V2[zd * 32 + lane];

            float rx = rij[3 * p], ry = rij[3 * p + 1], rz = rij[3 * p + 2];
            float inv = 1.0f / d;
            float ux = rx * inv, uy = ry * inv, uz = rz * inv;
            float tr3 = (ux * ux + uy * uy + uz * uz) * (1.0f / 3.0f);
            uxA[pi] = ux; uyA[pi] = uy; uzA[pi] = uz;
            txxA[pi] = ux * ux - tr3; tyyA[pi] = uy * uy - tr3; tzzA[pi] = uz * uz - tr3;
            txyA[pi] = ux * uy; txzA[pi] = ux * uz; tyzA[pi] = uy * uz;

            float ee  = __expf(-RBF_ALPHA * d);
            float dfm = ee - mlane;
            float rb  = __expf(-beta * dfm * dfm) * rc;
            rbf_w[lane * 4 + pi] = rb;

            C0[pi] = rc * (ubv.x + vb.x);
            C1[pi] = rc * (ubv.y + vb.y);
        }
        __syncwarp();

        ull g1[4] = {0, 0, 0, 0}, g2[4] = {0, 0, 0, 0}, g3[4] = {0, 0, 0, 0};
#pragma unroll
        for (int r = 0; r < R; r++) {
            float4 wA = sh_dpA[r * 32 + lane];
            float2 wB = sh_dpB[r * 32 + lane];
            float4 rq = sh_rbf[w][r];
            ull w1p = pk2(wA.x, wA.y);
            ull w2p = pk2(wA.z, wA.w);
            ull w3p = pk2(wB.x, wB.y);
            ull r0 = dup2(rq.x), r1 = dup2(rq.y), r2 = dup2(rq.z), r3 = dup2(rq.w);
            g1[0] = fma2_(r0, w1p, g1[0]); g2[0] = fma2_(r0, w2p, g2[0]); g3[0] = fma2_(r0, w3p, g3[0]);
            g1[1] = fma2_(r1, w1p, g1[1]); g2[1] = fma2_(r1, w2p, g2[1]); g3[1] = fma2_(r1, w3p, g3[1]);
            g1[2] = fma2_(r2, w1p, g1[2]); g2[2] = fma2_(r2, w2p, g2[2]); g3[2] = fma2_(r2, w3p, g3[2]);
            g1[3] = fma2_(r3, w1p, g1[3]); g2[3] = fma2_(r3, w2p, g2[3]); g3[3] = fma2_(r3, w3p, g3[3]);
        }
        __syncwarp();

#pragma unroll
        for (int pi = 0; pi < 4; pi++) {
            ull Cp = pk2(C0[pi], C1[pi]);
            ull f1 = mul2_(add2_(g1[pi], b1p), Cp);
            ull f2 = mul2_(mul2_(add2_(g2[pi], b2p), Cp), tenp);
            ull f3 = mul2_(mul2_(add2_(g3[pi], b3p), Cp), hunp);
            cI  = add2_(cI, f1);
            wx  = fma2_(f2, dup2(uxA[pi]),  wx);
            wy  = fma2_(f2, dup2(uyA[pi]),  wy);
            wz  = fma2_(f2, dup2(uzA[pi]),  wz);
            sxx = fma2_(f3, dup2(txxA[pi]), sxx);
            syy = fma2_(f3, dup2(tyyA[pi]), syy);
            szz = fma2_(f3, dup2(tzzA[pi]), szz);
            sxy = fma2_(f3, dup2(txyA[pi]), sxy);
            sxz = fma2_(f3, dup2(txzA[pi]), sxz);
            syz = fma2_(f3, dup2(tyzA[pi]), syz);
        }
    }

    float2 cIf = up2(cI),  wxf = up2(wx),  wyf = up2(wy),  wzf = up2(wz);
    float2 sxxf = up2(sxx), syyf = up2(syy), szzf = up2(szz);
    float2 sxyf = up2(sxy), sxzf = up2(sxz), syzf = up2(syz);

    float tA0 = cIf.x + sxxf.x, tB0 = cIf.x + syyf.x, tC0 = cIf.x + szzf.x;
    float tn0 = tA0*tA0 + tB0*tB0 + tC0*tC0
              + 2.0f * (sxyf.x*sxyf.x + wzf.x*wzf.x + sxzf.x*sxzf.x
                      + wyf.x*wyf.x + syzf.x*syzf.x + wxf.x*wxf.x);
    float tA1 = cIf.y + sxxf.y, tB1 = cIf.y + syyf.y, tC1 = cIf.y + szzf.y;
    float tn1 = tA1*tA1 + tB1*tB1 + tC1*tC1
              + 2.0f * (sxyf.y*sxyf.y + wzf.y*wzf.y + sxzf.y*sxzf.y
                      + wyf.y*wyf.y + syzf.y*syzf.y + wxf.y*wxf.y);

    float ssum = tn0 + tn1;
#pragma unroll
    for (int o = 16; o; o >>= 1) ssum += __shfl_xor_sync(0xffffffffu, ssum, o);
    float mu = ssum * (1.0f / 64.0f);
    float e0 = tn0 - mu, e1 = tn1 - mu;
    float vsum = e0 * e0 + e1 * e1;
#pragma unroll
    for (int o = 16; o; o >>= 1) vsum += __shfl_xor_sync(0xffffffffu, vsum, o);
    float rstd = rsqrtf(vsum * (1.0f / 64.0f) + 1e-5f);

    float2 lg = reinterpret_cast<const float2*>(lng)[lane];
    float2 lb = reinterpret_cast<const float2*>(lnb)[lane];
    float2 nrm;
    nrm.x = e0 * rstd * lg.x + lb.x;
    nrm.y = e1 * rstd * lg.y + lb.y;
    reinterpret_cast<float2*>(g_tnorm)[a * 32 + lane] = nrm;

    int oidx = a * 32 + lane;
    reinterpret_cast<float2*>(g_comp[0])[oidx] = cIf;
    reinterpret_cast<float2*>(g_comp[1])[oidx] = wxf;
    reinterpret_cast<float2*>(g_comp[2])[oidx] = wyf;
    reinterpret_cast<float2*>(g_comp[3])[oidx] = wzf;
    reinterpret_cast<float2*>(g_comp[4])[oidx] = sxxf;
    reinterpret_cast<float2*>(g_comp[5])[oidx] = syyf;
    reinterpret_cast<float2*>(g_comp[6])[oidx] = szzf;
    reinterpret_cast<float2*>(g_comp[7])[oidx] = sxyf;
    reinterpret_cast<float2*>(g_comp[8])[oidx] = sxzf;
    reinterpret_cast<float2*>(g_comp[9])[oidx] = syzf;
}

// ---------------- K_mlp ----------------
// 16 atoms/block, 256 threads. Activations transposed [k][aa] in shared;
// weights streamed from global (L1-resident); 16-atom register blocking, f32x2.
__global__ void __launch_bounds__(256) k_mlp(
    const float* __restrict__ ls1w, const float* __restrict__ ls1b,
    const float* __restrict__ ls2w, const float* __restrict__ ls2b) {
    __shared__ __align__(16) float nshT[64 * 16];
    __shared__ __align__(16) float h1T[128 * 16];

    int tid = threadIdx.x;
    int ab  = blockIdx.x * 16;

    for (int e = tid; e < 1024; e += 256) {
        int aa = e >> 6, k = e & 63;
        nshT[k * 16 + aa] = g_tnorm[(ab + aa) * 64 + k];
    }
    __syncthreads();

    // layer 1: 64 -> 128, silu
    {
        int j = tid & 127, half = tid >> 7;
        ull bp = dup2(ls1b[j]);
        ull a0 = bp, a1 = bp, a2 = bp, a3 = bp;
        const float4* wrow = reinterpret_cast<const float4*>(ls1w + j * 64);
#pragma unroll
        for (int k4 = 0; k4 < 16; k4++) {
            float4 wv = wrow[k4];
#pragma unroll
            for (int kk = 0; kk < 4; kk++) {
                float wsc = (kk == 0) ? wv.x : (kk == 1) ? wv.y : (kk == 2) ? wv.z : wv.w;
                ull wd = dup2(wsc);
                const ull* hp = reinterpret_cast<const ull*>(&nshT[(k4 * 4 + kk) * 16 + half * 8]);
                a0 = fma2_(wd, hp[0], a0);
                a1 = fma2_(wd, hp[1], a1);
                a2 = fma2_(wd, hp[2], a2);
                a3 = fma2_(wd, hp[3], a3);
            }
        }
        float rr[8]; float2 f;
        f = up2(a0); rr[0] = f.x; rr[1] = f.y;
        f = up2(a1); rr[2] = f.x; rr[3] = f.y;
        f = up2(a2); rr[4] = f.x; rr[5] = f.y;
        f = up2(a3); rr[6] = f.x; rr[7] = f.y;
#pragma unroll
        for (int i = 0; i < 8; i++) rr[i] = rr[i] / (1.0f + __expf(-rr[i]));
        float4* dst = reinterpret_cast<float4*>(&h1T[j * 16 + half * 8]);
        dst[0] = make_float4(rr[0], rr[1], rr[2], rr[3]);
        dst[1] = make_float4(rr[4], rr[5], rr[6], rr[7]);
    }
    __syncthreads();

    // layer 2: 128 -> 192, silu
    if (tid < 192) {
        int j = tid;
        ull bp = dup2(ls2b[j]);
        ull acc[8];
#pragma unroll
        for (int i = 0; i < 8; i++) acc[i] = bp;
        const float4* wrow = reinterpret_cast<const float4*>(ls2w + j * 128);
#pragma unroll 4
        for (int k4 = 0; k4 < 32; k4++) {
            float4 wv = wrow[k4];
#pragma unroll
            for (int kk = 0; kk < 4; kk++) {
                float wsc = (kk == 0) ? wv.x : (kk == 1) ? wv.y : (kk == 2) ? wv.z : wv.w;
                ull wd = dup2(wsc);
                const ull* hp = reinterpret_cast<const ull*>(&h1T[(k4 * 4 + kk) * 16]);
#pragma unroll
                for (int i = 0; i < 8; i++) acc[i] = fma2_(wd, hp[i], acc[i]);
            }
        }
#pragma unroll
        for (int i = 0; i < 8; i++) {
            float2 f = up2(acc[i]);
            float v0 = f.x / (1.0f + __expf(-f.x));
            float v1 = f.y / (1.0f + __expf(-f.y));
            g_mlp[(ab + 2 * i)     * 192 + j] = v0;
            g_mlp[(ab + 2 * i + 1) * 192 + j] = v1;
        }
    }
}

// ---------------- K_final ----------------
// 16 atoms/block, 640 threads = (comp c 0..9) x (g 0..63). 16-atom register
// blocking with f32x2; lt weights read per-thread as row g (L1-resident).
#define RES_CSTRIDE 1160   // 64*18 + 8 pad: shifts comp blocks by 8 banks
__global__ void __launch_bounds__(640) k_final(
    const float* __restrict__ lt0, const float* __restrict__ lt1,
    const float* __restrict__ lt2, float* __restrict__ out) {
    extern __shared__ float sm[];
    float* csh = sm;                        // [(c*64+h)*16+aa]  10240
    float* res = csh + 10240;               // [c*1160 + g*18 + aa] 11600
    float* nm  = res + 11600;               // [aa*192 + j] 3072

    int tid = threadIdx.x;
    int ab  = blockIdx.x * 16;

    for (int e = tid; e < 10240; e += 640) {
        int aa = e / 640;
        int rem = e - aa * 640;
        int c = rem >> 6, h = rem & 63;
        csh[(c * 64 + h) * 16 + aa] = g_comp[c][(ab + aa) * 64 + h];
    }
    for (int e = tid; e < 3072; e += 640) nm[e] = g_mlp[ab * 192 + e];
    __syncthreads();

    {
        int c = tid / 64, g = tid & 63;
        const float* wp = (c == 0) ? lt0 : (c < 4) ? lt1 : lt2;
        // einsum 'nhij,gh->ngij': weight indexed [g][h] -> read row g
        const float4* wrow4 = reinterpret_cast<const float4*>(wp + g * 64);
        ull acc[8];
#pragma unroll
        for (int i = 0; i < 8; i++) acc[i] = 0ull;
#pragma unroll 4
        for (int h4 = 0; h4 < 16; h4++) {
            float4 wv = wrow4[h4];
#pragma unroll
            for (int kk = 0; kk < 4; kk++) {
                float wsc = (kk == 0) ? wv.x : (kk == 1) ? wv.y : (kk == 2) ? wv.z : wv.w;
                ull wd = dup2(wsc);
                const ulonglong2* cp =
                    reinterpret_cast<const ulonglong2*>(&csh[(c * 64 + h4 * 4 + kk) * 16]);
#pragma unroll
                for (int i = 0; i < 4; i++) {
                    ulonglong2 q = cp[i];
                    acc[2 * i]     = fma2_(wd, q.x, acc[2 * i]);
                    acc[2 * i + 1] = fma2_(wd, q.y, acc[2 * i + 1]);
                }
            }
        }
        ull* rp = reinterpret_cast<ull*>(&res[c * RES_CSTRIDE + g * 18]);
#pragma unroll
        for (int i = 0; i < 8; i++) rp[i] = acc[i];
    }
    __syncthreads();

    // assemble 3x3 outputs: out linear index = ab*576 + e (fully coalesced)
    for (int e = tid; e < 9216; e += 640) {
        int aa = e / 576;
        int rem = e - aa * 576;
        int g2 = rem / 9;
        int ij = rem - g2 * 9;
        int i3 = (ij * 11) >> 5;       // ij / 3
        int jc = ij - i3 * 3;
        bool dg = (i3 == jc);
        int sidx = dg ? (4 + i3) : (6 + i3 + jc);
        int aidx = dg ? 1 : (4 - (i3 + jc));
        float sgn = dg ? 0.0f : ((((i3 - jc) + 3) % 3 == 1) ? 1.0f : -1.0f);
        float n0 = nm[aa * 192 + g2 * 3 + 0];
        float n1 = nm[aa * 192 + g2 * 3 + 1];
        float n2 = nm[aa * 192 + g2 * 3 + 2];
        float cIv = res[g2 * 18 + aa];
        float av  = res[aidx * RES_CSTRIDE + g2 * 18 + aa];
        float sv  = res[sidx * RES_CSTRIDE + g2 * 18 + aa];
        float iv = dg ? cIv : 0.0f;
        out[ab * 576 + e] = iv * n0 + sgn * av * n1 + sv * n2;
    }
}

// ---------------- launch ----------------
extern "C" void kernel_launch(void* const* d_in, const int* in_sizes, int n_in,
                              void* d_out, int out_size) {
    const int*   anum  = (const int*)d_in[0];
    const int*   psrc  = (const int*)d_in[1];
    const int*   pdst  = psrc + N_PAIRS;
    const float* dij   = (const float*)d_in[2];
    const float* rij   = (const float*)d_in[3];
    const float* emb   = (const float*)d_in[4];
    const float* e2w   = (const float*)d_in[5];
    const float* e2b   = (const float*)d_in[6];
    const float* dp1w  = (const float*)d_in[7];
    const float* dp1b  = (const float*)d_in[8];
    const float* dp2w  = (const float*)d_in[9];
    const float* dp2b  = (const float*)d_in[10];
    const float* dp3w  = (const float*)d_in[11];
    const float* dp3b  = (const float*)d_in[12];
    const float* lt0   = (const float*)d_in[13];
    const float* lt1   = (const float*)d_in[14];
    const float* lt2   = (const float*)d_in[15];
    const float* ls1w  = (const float*)d_in[16];
    const float* ls1b  = (const float*)d_in[17];
    const float* ls2w  = (const float*)d_in[18];
    const float* ls2b  = (const float*)d_in[19];
    const float* lng   = (const float*)d_in[20];
    const float* lnb   = (const float*)d_in[21];
    float* out = (float*)d_out;

    const size_t final_smem = (10240 + 11600 + 3072) * sizeof(float);
    cudaFuncSetAttribute(k_final, cudaFuncAttributeMaxDynamicSharedMemorySize, (int)final_smem);

    k_uv<<<MAX_Z, H>>>(emb, e2w, e2b);
    k_zero<<<(N_ATOMS + 255) / 256, 256>>>();
    k_hist<<<(N_PAIRS + 255) / 256, 256>>>(psrc);
    k_scan<<<1, 1024>>>();
    k_scatter<<<(N_PAIRS + 255) / 256, 256>>>(psrc);
    k_pairs<<<N_ATOMS / 8, 256>>>(anum, pdst, dij, rij,
                                  dp1w, dp2w, dp3w, dp1b, dp2b, dp3b, lng, lnb);
    k_mlp<<<N_ATOMS / 16, 256>>>(ls1w, ls1b, ls2w, ls2b);
    k_final<<<N_ATOMS / 16, 640, final_smem>>>(lt0, lt1, lt2, out);
}

// round 4
// speedup vs baseline: 1.7875x; 1.0214x over previous
#include <cuda_runtime.h>
#include <math.h>

#define N_ATOMS 10000
#define N_PAIRS 100000
#define H 64
#define R 32
#define MAX_Z 100

typedef unsigned long long ull;

// -------- f32x2 packed math helpers (sm_10x) --------
__device__ __forceinline__ ull pk2(float x, float y) {
    ull r; asm("mov.b64 %0,{%1,%2};" : "=l"(r) : "f"(x), "f"(y)); return r;
}
__device__ __forceinline__ float2 up2(ull v) {
    float2 f; asm("mov.b64 {%0,%1},%2;" : "=f"(f.x), "=f"(f.y) : "l"(v)); return f;
}
__device__ __forceinline__ ull dup2(float x) { return pk2(x, x); }
__device__ __forceinline__ ull fma2_(ull a, ull b, ull c) {
    ull d; asm("fma.rn.f32x2 %0,%1,%2,%3;" : "=l"(d) : "l"(a), "l"(b), "l"(c)); return d;
}
__device__ __forceinline__ ull add2_(ull a, ull b) {
    ull d; asm("add.rn.f32x2 %0,%1,%2;" : "=l"(d) : "l"(a), "l"(b)); return d;
}
__device__ __forceinline__ ull mul2_(ull a, ull b) {
    ull d; asm("mul.rn.f32x2 %0,%1,%2;" : "=l"(d) : "l"(a), "l"(b)); return d;
}

// ---------------- scratch ----------------
__device__ __align__(16) float g_U[MAX_Z * H];
__device__ __align__(16) float g_V[MAX_Z * H];
__device__ int   g_counts[N_ATOMS];            // zero-init; self-cleaned by k_scan
__device__ int   g_offsets[N_ATOMS + 1];
__device__ int   g_cursor[N_ATOMS];
__device__ __align__(16) float4 g_geoA[N_PAIRS];   // ux,uy,uz,rc   (slot-ordered)
__device__ __align__(16) float4 g_geoB[N_PAIRS];   // txx,tyy,tzz,zd(bits)
__device__ __align__(16) float4 g_geoC[N_PAIRS];   // txy,txz,tyz,pad
__device__ __align__(16) float  g_rbf[N_PAIRS * R];// slot-ordered, rc folded in
__device__ __align__(16) float g_comp[10][N_ATOMS * H];
__device__ __align__(16) float g_tnorm[N_ATOMS * H];

#define RBF_START 0.60653065971263342f
#define RBF_ALPHA 10.0f

// ---------------- K1: embedding transform ----------------
__global__ void k_uv(const float* __restrict__ emb, const float* __restrict__ w2,
                     const float* __restrict__ b2) {
    __shared__ float se[H];
    int t = blockIdx.x;
    int h = threadIdx.x;
    se[h] = emb[t * H + h];
    __syncthreads();
    float u = b2[h];
    float v = 0.0f;
    const float* wr = w2 + h * 2 * H;
#pragma unroll
    for (int k = 0; k < H; k++) {
        u += se[k] * wr[k];
        v += se[k] * wr[H + k];
    }
    g_U[t * H + h] = u;
    g_V[t * H + h] = v;
}

// ---------------- histogram ----------------
__global__ void k_hist(const int* __restrict__ src) {
    int i = blockIdx.x * blockDim.x + threadIdx.x;
    if (i < N_PAIRS) atomicAdd(&g_counts[src[i]], 1);
}

// ---------------- scan (and self-clean counts for next replay) ----------------
__global__ void k_scan() {
    __shared__ int wsum[32];
    int t = threadIdx.x;
    int lane = t & 31, wid = t >> 5;
    int base = t * 10;
    int loc[10];
    int s = 0;
#pragma unroll
    for (int i = 0; i < 10; i++) {
        int idx = base + i;
        int c = (idx < N_ATOMS) ? g_counts[idx] : 0;
        loc[i] = s;
        s += c;
    }
    int v = s;
#pragma unroll
    for (int o = 1; o < 32; o <<= 1) {
        int u = __shfl_up_sync(0xffffffffu, v, o);
        if (lane >= o) v += u;
    }
    if (lane == 31) wsum[wid] = v;
    __syncthreads();
    if (wid == 0) {
        int x = wsum[lane];
#pragma unroll
        for (int o = 1; o < 32; o <<= 1) {
            int u = __shfl_up_sync(0xffffffffu, x, o);
            if (lane >= o) x += u;
        }
        wsum[lane] = x;
    }
    __syncthreads();
    int wbase = (wid > 0) ? wsum[wid - 1] : 0;
    int excl = wbase + v - s;
#pragma unroll
    for (int i = 0; i < 10; i++) {
        int idx = base + i;
        if (idx < N_ATOMS) {
            int o = excl + loc[i];
            g_offsets[idx] = o;
            g_cursor[idx]  = o;
            g_counts[idx]  = 0;   // restore invariant for next replay
        }
    }
    if (t == 1023) g_offsets[N_ATOMS] = wbase + v;
}

// ---------------- K_prep: scatter + per-pair geometry + rbf (slot-ordered) ----------
__global__ void __launch_bounds__(256) k_prep(
    const int* __restrict__ src, const int* __restrict__ pdst,
    const int* __restrict__ anum,
    const float* __restrict__ dij, const float* __restrict__ rij) {
    int i = blockIdx.x * 256 + threadIdx.x;
    int lane = threadIdx.x & 31;
    if ((i & ~31) >= N_PAIRS) return;       // whole-warp invalid (N_PAIRS % 32 == 0)

    float d = dij[i];
    float rc = (d < 0.5f) ? 0.5f * (__cosf(6.2831853071795865f * d) + 1.0f) : 0.0f;
    int zd = anum[pdst[i]];

    float rx = rij[3 * i], ry = rij[3 * i + 1], rz = rij[3 * i + 2];
    float inv = 1.0f / d;
    float ux = rx * inv, uy = ry * inv, uz = rz * inv;
    float tr3 = (ux * ux + uy * uy + uz * uz) * (1.0f / 3.0f);
    float ee = __expf(-RBF_ALPHA * d);

    int pos = atomicAdd(&g_cursor[src[i]], 1);
    g_geoA[pos] = make_float4(ux, uy, uz, rc);
    g_geoB[pos] = make_float4(ux * ux - tr3, uy * uy - tr3, uz * uz - tr3,
                              __int_as_float(zd));
    g_geoC[pos] = make_float4(ux * uy, ux * uz, uy * uz, 0.0f);

    // warp-cooperative rbf: lane = r, pair broadcast via shfl
    const float rbf_step = (1.0f - RBF_START) * (1.0f / 31.0f);
    float tb = (1.0f - RBF_START) * (2.0f / 32.0f);
    const float beta = 1.0f / (tb * tb);
    const float mlane = RBF_START + rbf_step * (float)lane;
#pragma unroll 4
    for (int j = 0; j < 32; j++) {
        float ee_b  = __shfl_sync(0xffffffffu, ee,  j);
        float rc_b  = __shfl_sync(0xffffffffu, rc,  j);
        int   pos_b = __shfl_sync(0xffffffffu, pos, j);
        float dfm = ee_b - mlane;
        g_rbf[pos_b * 32 + lane] = __expf(-beta * dfm * dfm) * rc_b;
    }
}

// ---------------- K_pairs: streaming accumulation + layernorm ----------------
// warp per atom; lane owns h = 2*lane, 2*lane+1; pairs batched 4-wide.
__global__ void __launch_bounds__(256) k_pairs(
    const int* __restrict__ anum,
    const float* __restrict__ dp1w, const float* __restrict__ dp2w,
    const float* __restrict__ dp3w,
    const float* __restrict__ dp1b, const float* __restrict__ dp2b,
    const float* __restrict__ dp3b,
    const float* __restrict__ lng, const float* __restrict__ lnb) {
    __shared__ __align__(16) float4 sh_dpA[R * 32];   // (w1_h0,w1_h1,w2_h0,w2_h1)
    __shared__ __align__(16) float2 sh_dpB[R * 32];   // (w3_h0,w3_h1)
    __shared__ __align__(16) float4 sh_rbf[8][R];     // [warp][r] = 4 pairs

    for (int e = threadIdx.x; e < R * 32; e += 256) {
        int r = e >> 5, l = e & 31;
        int h0 = 2 * l, h1 = 2 * l + 1;
        sh_dpA[e] = make_float4(dp1w[h0 * R + r], dp1w[h1 * R + r],
                                dp2w[h0 * R + r], dp2w[h1 * R + r]);
        sh_dpB[e] = make_float2(dp3w[h0 * R + r], dp3w[h1 * R + r]);
    }
    __syncthreads();

    int w    = threadIdx.x >> 5;
    int lane = threadIdx.x & 31;
    int a    = blockIdx.x * 8 + w;

    int start = g_offsets[a];
    int end   = g_offsets[a + 1];
    int za    = anum[a];

    const float2* U2 = reinterpret_cast<const float2*>(g_U);
    const float2* V2 = reinterpret_cast<const float2*>(g_V);
    float2 ubv = U2[za * 32 + lane];
    float2 b1v = reinterpret_cast<const float2*>(dp1b)[lane];
    float2 b2v = reinterpret_cast<const float2*>(dp2b)[lane];
    float2 b3v = reinterpret_cast<const float2*>(dp3b)[lane];
    ull b1p = pk2(b1v.x, b1v.y);
    ull b2p = pk2(b2v.x, b2v.y);
    ull b3p = pk2(b3v.x, b3v.y);
    const ull tenp = dup2(10.0f);
    const ull hunp = dup2(100.0f);

    ull cI = 0, wx = 0, wy = 0, wz = 0;
    ull sxx = 0, syy = 0, szz = 0, sxy = 0, sxz = 0, syz = 0;

    for (int it = start; it < end; it += 4) {
        // phase A: stream rbf rows for 4 pairs into shared (coalesced LDG.128-wide rows)
        float rbv[4];
#pragma unroll
        for (int pi = 0; pi < 4; pi++) {
            int idx = it + pi;
            rbv[pi] = (idx < end) ? g_rbf[idx * 32 + lane] : 0.0f;
        }
        __syncwarp();
        sh_rbf[w][lane] = make_float4(rbv[0], rbv[1], rbv[2], rbv[3]);
        __syncwarp();

        // phase B: rbf @ dp weights (packed f32x2)
        ull g1[4] = {0, 0, 0, 0}, g2[4] = {0, 0, 0, 0}, g3[4] = {0, 0, 0, 0};
#pragma unroll
        for (int r = 0; r < R; r++) {
            float4 wA = sh_dpA[r * 32 + lane];
            float2 wB = sh_dpB[r * 32 + lane];
            float4 rq = sh_rbf[w][r];
            ull w1p = pk2(wA.x, wA.y);
            ull w2p = pk2(wA.z, wA.w);
            ull w3p = pk2(wB.x, wB.y);
            ull r0 = dup2(rq.x), r1 = dup2(rq.y), r2 = dup2(rq.z), r3 = dup2(rq.w);
            g1[0] = fma2_(r0, w1p, g1[0]); g2[0] = fma2_(r0, w2p, g2[0]); g3[0] = fma2_(r0, w3p, g3[0]);
            g1[1] = fma2_(r1, w1p, g1[1]); g2[1] = fma2_(r1, w2p, g2[1]); g3[1] = fma2_(r1, w3p, g3[1]);
            g1[2] = fma2_(r2, w1p, g1[2]); g2[2] = fma2_(r2, w2p, g2[2]); g3[2] = fma2_(r2, w3p, g3[2]);
            g1[3] = fma2_(r3, w1p, g1[3]); g2[3] = fma2_(r3, w2p, g2[3]); g3[3] = fma2_(r3, w3p, g3[3]);
        }
        __syncwarp();

        // phase C: per-pair scale + accumulate (geo loads are L1 broadcast)
#pragma unroll
        for (int pi = 0; pi < 4; pi++) {
            int idx = it + pi;
            if (idx < end) {
                float4 gA = g_geoA[idx];
                float4 gB = g_geoB[idx];
                float4 gC = g_geoC[idx];
                int zd = __float_as_int(gB.w);
                float2 vb = V2[zd * 32 + lane];
                float rc = gA.w;
                ull Cp = pk2(rc * (ubv.x + vb.x), rc * (ubv.y + vb.y));
                ull f1 = mul2_(add2_(g1[pi], b1p), Cp);
                ull f2 = mul2_(mul2_(add2_(g2[pi], b2p), Cp), tenp);
                ull f3 = mul2_(mul2_(add2_(g3[pi], b3p), Cp), hunp);
                cI  = add2_(cI, f1);
                wx  = fma2_(f2, dup2(gA.x), wx);
                wy  = fma2_(f2, dup2(gA.y), wy);
                wz  = fma2_(f2, dup2(gA.z), wz);
                sxx = fma2_(f3, dup2(gB.x), sxx);
                syy = fma2_(f3, dup2(gB.y), syy);
                szz = fma2_(f3, dup2(gB.z), szz);
                sxy = fma2_(f3, dup2(gC.x), sxy);
                sxz = fma2_(f3, dup2(gC.y), sxz);
                syz = fma2_(f3, dup2(gC.z), syz);
            }
        }
    }

    float2 cIf = up2(cI),  wxf = up2(wx),  wyf = up2(wy),  wzf = up2(wz);
    float2 sxxf = up2(sxx), syyf = up2(syy), szzf = up2(szz);
    float2 sxyf = up2(sxy), sxzf = up2(sxz), syzf = up2(syz);

    float tA0 = cIf.x + sxxf.x, tB0 = cIf.x + syyf.x, tC0 = cIf.x + szzf.x;
    float tn0 = tA0*tA0 + tB0*tB0 + tC0*tC0
              + 2.0f * (sxyf.x*sxyf.x + wzf.x*wzf.x + sxzf.x*sxzf.x
                      + wyf.x*wyf.x + syzf.x*syzf.x + wxf.x*wxf.x);
    float tA1 = cIf.y + sxxf.y, tB1 = cIf.y + syyf.y, tC1 = cIf.y + szzf.y;
    float tn1 = tA1*tA1 + tB1*tB1 + tC1*tC1
              + 2.0f * (sxyf.y*sxyf.y + wzf.y*wzf.y + sxzf.y*sxzf.y
                      + wyf.y*wyf.y + syzf.y*syzf.y + wxf.y*wxf.y);

    float ssum = tn0 + tn1;
#pragma unroll
    for (int o = 16; o; o >>= 1) ssum += __shfl_xor_sync(0xffffffffu, ssum, o);
    float mu = ssum * (1.0f / 64.0f);
    float e0 = tn0 - mu, e1 = tn1 - mu;
    float vsum = e0 * e0 + e1 * e1;
#pragma unroll
    for (int o = 16; o; o >>= 1) vsum += __shfl_xor_sync(0xffffffffu, vsum, o);
    float rstd = rsqrtf(vsum * (1.0f / 64.0f) + 1e-5f);

    float2 lg = reinterpret_cast<const float2*>(lng)[lane];
    float2 lb = reinterpret_cast<const float2*>(lnb)[lane];
    float2 nrm;
    nrm.x = e0 * rstd * lg.x + lb.x;
    nrm.y = e1 * rstd * lg.y + lb.y;
    reinterpret_cast<float2*>(g_tnorm)[a * 32 + lane] = nrm;

    int oidx = a * 32 + lane;
    reinterpret_cast<float2*>(g_comp[0])[oidx] = cIf;
    reinterpret_cast<float2*>(g_comp[1])[oidx] = wxf;
    reinterpret_cast<float2*>(g_comp[2])[oidx] = wyf;
    reinterpret_cast<float2*>(g_comp[3])[oidx] = wzf;
    reinterpret_cast<float2*>(g_comp[4])[oidx] = sxxf;
    reinterpret_cast<float2*>(g_comp[5])[oidx] = syyf;
    reinterpret_cast<float2*>(g_comp[6])[oidx] = szzf;
    reinterpret_cast<float2*>(g_comp[7])[oidx] = sxyf;
    reinterpret_cast<float2*>(g_comp[8])[oidx] = sxzf;
    reinterpret_cast<float2*>(g_comp[9])[oidx] = syzf;
}

// ---------------- K_mlpfinal: MLP + channel-mix GEMM + 3x3 assembly fused -----
// 16 atoms/block, 640 threads.
#define RES_CSTRIDE 1160   // 64*18 + 8 pad
__global__ void __launch_bounds__(640) k_mlpfinal(
    const float* __restrict__ ls1w, const float* __restrict__ ls1b,
    const float* __restrict__ ls2w, const float* __restrict__ ls2b,
    const float* __restrict__ lt0, const float* __restrict__ lt1,
    const float* __restrict__ lt2, float* __restrict__ out) {
    extern __shared__ float sm[];
    float* csh  = sm;                        // [(c*64+h)*16+aa]        10240
    float* res  = csh + 10240;               // [c*1160 + g*18 + aa]    11600
    float* nm   = res + 11600;               // [aa*192 + j]             3072
    float* nshT = nm + 3072;                 // [k*16+aa]                1024
    float* h1T  = nshT + 1024;               // [j*16+aa]                2048

    int tid = threadIdx.x;
    int ab  = blockIdx.x * 16;

    for (int e = tid; e < 10240; e += 640) {
        int aa = e / 640;
        int rem = e - aa * 640;
        int c = rem >> 6, h = rem & 63;
        csh[(c * 64 + h) * 16 + aa] = g_comp[c][(ab + aa) * 64 + h];
    }
    for (int e = tid; e < 1024; e += 640) {
        int aa = e >> 6, k = e & 63;
        nshT[k * 16 + aa] = g_tnorm[(ab + aa) * 64 + k];
    }
    __syncthreads();

    // ---- channel-mix GEMM: res[c][g][aa] = sum_h lt_m[g][h] * comp[c][h][aa]
    {
        int c = tid / 64, g = tid & 63;
        const float* wp = (c == 0) ? lt0 : (c < 4) ? lt1 : lt2;
        const float4* wrow4 = reinterpret_cast<const float4*>(wp + g * 64);
        ull acc[8];
#pragma unroll
        for (int i = 0; i < 8; i++) acc[i] = 0ull;
#pragma unroll 4
        for (int h4 = 0; h4 < 16; h4++) {
            float4 wv = wrow4[h4];
#pragma unroll
            for (int kk = 0; kk < 4; kk++) {
                float wsc = (kk == 0) ? wv.x : (kk == 1) ? wv.y : (kk == 2) ? wv.z : wv.w;
                ull wd = dup2(wsc);
                const ulonglong2* cp =
                    reinterpret_cast<const ulonglong2*>(&csh[(c * 64 + h4 * 4 + kk) * 16]);
#pragma unroll
                for (int i = 0; i < 4; i++) {
                    ulonglong2 q = cp[i];
                    acc[2 * i]     = fma2_(wd, q.x, acc[2 * i]);
                    acc[2 * i + 1] = fma2_(wd, q.y, acc[2 * i + 1]);
                }
            }
        }
        ull* rp = reinterpret_cast<ull*>(&res[c * RES_CSTRIDE + g * 18]);
#pragma unroll
        for (int i = 0; i < 8; i++) rp[i] = acc[i];
    }
    __syncthreads();

    // ---- MLP layer 1: 64 -> 128, silu (256 threads)
    if (tid < 256) {
        int j = tid & 127, half = tid >> 7;
        ull bp = dup2(ls1b[j]);
        ull a0 = bp, a1 = bp, a2 = bp, a3 = bp;
        const float4* wrow = reinterpret_cast<const float4*>(ls1w + j * 64);
#pragma unroll
        for (int k4 = 0; k4 < 16; k4++) {
            float4 wv = wrow[k4];
#pragma unroll
            for (int kk = 0; kk < 4; kk++) {
                float wsc = (kk == 0) ? wv.x : (kk == 1) ? wv.y : (kk == 2) ? wv.z : wv.w;
                ull wd = dup2(wsc);
                const ull* hp = reinterpret_cast<const ull*>(&nshT[(k4 * 4 + kk) * 16 + half * 8]);
                a0 = fma2_(wd, hp[0], a0);
                a1 = fma2_(wd, hp[1], a1);
                a2 = fma2_(wd, hp[2], a2);
                a3 = fma2_(wd, hp[3], a3);
            }
        }
        float rr[8]; float2 f;
        f = up2(a0); rr[0] = f.x; rr[1] = f.y;
        f = up2(a1); rr[2] = f.x; rr[3] = f.y;
        f = up2(a2); rr[4] = f.x; rr[5] = f.y;
        f = up2(a3); rr[6] = f.x; rr[7] = f.y;
#pragma unroll
        for (int i = 0; i < 8; i++) rr[i] = rr[i] / (1.0f + __expf(-rr[i]));
        float4* dst = reinterpret_cast<float4*>(&h1T[j * 16 + half * 8]);
        dst[0] = make_float4(rr[0], rr[1], rr[2], rr[3]);
        dst[1] = make_float4(rr[4], rr[5], rr[6], rr[7]);
    }
    __syncthreads();

    // ---- MLP layer 2: 128 -> 192, silu (192 threads) -> nm in shared
    if (tid < 192) {
        int j = tid;
        ull bp = dup2(ls2b[j]);
        ull acc[8];
#pragma unroll
        for (int i = 0; i < 8; i++) acc[i] = bp;
        const float4* wrow = reinterpret_cast<const float4*>(ls2w + j * 128);
#pragma unroll 4
        for (int k4 = 0; k4 < 32; k4++) {
            float4 wv = wrow[k4];
#pragma unroll
            for (int kk = 0; kk < 4; kk++) {
                float wsc = (kk == 0) ? wv.x : (kk == 1) ? wv.y : (kk == 2) ? wv.z : wv.w;
                ull wd = dup2(wsc);
                const ull* hp = reinterpret_cast<const ull*>(&h1T[(k4 * 4 + kk) * 16]);
#pragma unroll
                for (int i = 0; i < 8; i++) acc[i] = fma2_(wd, hp[i], acc[i]);
            }
        }
#pragma unroll
        for (int i = 0; i < 8; i++) {
            float2 f = up2(acc[i]);
            nm[(2 * i)     * 192 + j] = f.x / (1.0f + __expf(-f.x));
            nm[(2 * i + 1) * 192 + j] = f.y / (1.0f + __expf(-f.y));
        }
    }
    __syncthreads();

    // ---- assemble 3x3 outputs (coalesced)
    for (int e = tid; e < 9216; e += 640) {
        int aa = e / 576;
        int rem = e - aa * 576;
        int g2 = rem / 9;
        int ij = rem - g2 * 9;
        int i3 = (ij * 11) >> 5;
        int jc = ij - i3 * 3;
        bool dg = (i3 == jc);
        int sidx = dg ? (4 + i3) : (6 + i3 + jc);
        int aidx = dg ? 1 : (4 - (i3 + jc));
        float sgn = dg ? 0.0f : ((((i3 - jc) + 3) % 3 == 1) ? 1.0f : -1.0f);
        float n0 = nm[aa * 192 + g2 * 3 + 0];
        float n1 = nm[aa * 192 + g2 * 3 + 1];
        float n2 = nm[aa * 192 + g2 * 3 + 2];
        float cIv = res[g2 * 18 + aa];
        float av  = res[aidx * RES_CSTRIDE + g2 * 18 + aa];
        float sv  = res[sidx * RES_CSTRIDE + g2 * 18 + aa];
        float iv = dg ? cIv : 0.0f;
        out[ab * 576 + e] = iv * n0 + sgn * av * n1 + sv * n2;
    }
}

// ---------------- launch ----------------
extern "C" void kernel_launch(void* const* d_in, const int* in_sizes, int n_in,
                              void* d_out, int out_size) {
    const int*   anum  = (const int*)d_in[0];
    const int*   psrc  = (const int*)d_in[1];
    const int*   pdst  = psrc + N_PAIRS;
    const float* dij   = (const float*)d_in[2];
    const float* rij   = (const float*)d_in[3];
    const float* emb   = (const float*)d_in[4];
    const float* e2w   = (const float*)d_in[5];
    const float* e2b   = (const float*)d_in[6];
    const float* dp1w  = (const float*)d_in[7];
    const float* dp1b  = (const float*)d_in[8];
    const float* dp2w  = (const float*)d_in[9];
    const float* dp2b  = (const float*)d_in[10];
    const float* dp3w  = (const float*)d_in[11];
    const float* dp3b  = (const float*)d_in[12];
    const float* lt0   = (const float*)d_in[13];
    const float* lt1   = (const float*)d_in[14];
    const float* lt2   = (const float*)d_in[15];
    const float* ls1w  = (const float*)d_in[16];
    const float* ls1b  = (const float*)d_in[17];
    const float* ls2w  = (const float*)d_in[18];
    const float* ls2b  = (const float*)d_in[19];
    const float* lng   = (const float*)d_in[20];
    const float* lnb   = (const float*)d_in[21];
    float* out = (float*)d_out;

    const size_t fused_smem = (10240 + 11600 + 3072 + 1024 + 2048) * sizeof(float);
    cudaFuncSetAttribute(k_mlpfinal, cudaFuncAttributeMaxDynamicSharedMemorySize,
                         (int)fused_smem);

    k_uv<<<MAX_Z, H>>>(emb, e2w, e2b);
    k_hist<<<(N_PAIRS + 255) / 256, 256>>>(psrc);
    k_scan<<<1, 1024>>>();
    k_prep<<<(N_PAIRS + 255) / 256, 256>>>(psrc, pdst, anum, dij, rij);
    k_pairs<<<N_ATOMS / 8, 256>>>(anum, dp1w, dp2w, dp3w, dp1b, dp2b, dp3b, lng, lnb);
    k_mlpfinal<<<N_ATOMS / 16, 640, fused_smem>>>(ls1w, ls1b, ls2w, ls2b,
                                                  lt0, lt1, lt2, out);
}

// round 5
// speedup vs baseline: 2.0195x; 1.1298x over previous
#include <cuda_runtime.h>
#include <math.h>

#define N_ATOMS 10000
#define N_PAIRS 100000
#define H 64
#define R 32
#define MAX_Z 100

typedef unsigned long long ull;

// -------- f32x2 packed math helpers (sm_10x) --------
__device__ __forceinline__ ull pk2(float x, float y) {
    ull r; asm("mov.b64 %0,{%1,%2};" : "=l"(r) : "f"(x), "f"(y)); return r;
}
__device__ __forceinline__ float2 up2(ull v) {
    float2 f; asm("mov.b64 {%0,%1},%2;" : "=f"(f.x), "=f"(f.y) : "l"(v)); return f;
}
__device__ __forceinline__ ull dup2(float x) { return pk2(x, x); }
__device__ __forceinline__ ull fma2_(ull a, ull b, ull c) {
    ull d; asm("fma.rn.f32x2 %0,%1,%2,%3;" : "=l"(d) : "l"(a), "l"(b), "l"(c)); return d;
}
__device__ __forceinline__ ull add2_(ull a, ull b) {
    ull d; asm("add.rn.f32x2 %0,%1,%2;" : "=l"(d) : "l"(a), "l"(b)); return d;
}
__device__ __forceinline__ ull mul2_(ull a, ull b) {
    ull d; asm("mul.rn.f32x2 %0,%1,%2;" : "=l"(d) : "l"(a), "l"(b)); return d;
}

// ---------------- scratch ----------------
__device__ __align__(16) float g_U[MAX_Z * H];
__device__ __align__(16) float g_V[MAX_Z * H];
__device__ __align__(16) float g_ltT[3 * H * H];   // [m][h][g] transposed weights
__device__ int   g_counts[N_ATOMS];                // zero-init; self-cleaned by k_scan
__device__ int   g_offsets[N_ATOMS + 1];
__device__ int   g_cursor[N_ATOMS];
__device__ __align__(16) float4 g_geoA[N_PAIRS];   // ux,uy,uz,rc   (slot-ordered)
__device__ __align__(16) float4 g_geoB[N_PAIRS];   // txx,tyy,tzz,zd(bits)
__device__ __align__(16) float4 g_geoC[N_PAIRS];   // txy,txz,tyz,pad
__device__ __align__(16) float  g_rbf[N_PAIRS * R];
__device__ __align__(16) float g_comp[10][N_ATOMS * H];
__device__ __align__(16) float g_tnorm[N_ATOMS * H];

#define RBF_START 0.60653065971263342f
#define RBF_ALPHA 10.0f

#define HIST_BLOCKS 391
#define UV_BLOCKS   25      // 4 types per block
#define LTT_BLOCKS  48      // 12288 / 256
#define PRE_BLOCKS  (HIST_BLOCKS + UV_BLOCKS + LTT_BLOCKS)

// ---------------- K_pre: hist + embedding transform + lt transpose ----------------
__global__ void __launch_bounds__(256) k_pre(
    const int* __restrict__ src,
    const float* __restrict__ emb, const float* __restrict__ w2,
    const float* __restrict__ b2,
    const float* __restrict__ lt0, const float* __restrict__ lt1,
    const float* __restrict__ lt2) {
    int b = blockIdx.x;
    int tid = threadIdx.x;
    if (b < HIST_BLOCKS) {
        int i = b * 256 + tid;
        if (i < N_PAIRS) atomicAdd(&g_counts[src[i]], 1);
    } else if (b < HIST_BLOCKS + UV_BLOCKS) {
        __shared__ float se[4][H];
        int ty = tid >> 6;                       // type-in-block 0..3
        int h  = tid & 63;
        int t  = (b - HIST_BLOCKS) * 4 + ty;     // 0..99
        se[ty][h] = emb[t * H + h];
        __syncthreads();
        float u = b2[h];
        float v = 0.0f;
        const float* wr = w2 + h * 2 * H;
#pragma unroll
        for (int k = 0; k < H; k++) {
            u += se[ty][k] * wr[k];
            v += se[ty][k] * wr[H + k];
        }
        g_U[t * H + h] = u;
        g_V[t * H + h] = v;
    } else {
        int idx = (b - HIST_BLOCKS - UV_BLOCKS) * 256 + tid;   // < 12288
        int m = idx >> 12;
        int rem = idx & 4095;
        int g = rem >> 6, h = rem & 63;
        const float* s = (m == 0) ? lt0 : (m == 1) ? lt1 : lt2;
        g_ltT[m * 4096 + h * 64 + g] = s[rem];
    }
}

// ---------------- scan (and self-clean counts) ----------------
__global__ void k_scan() {
    __shared__ int wsum[32];
    int t = threadIdx.x;
    int lane = t & 31, wid = t >> 5;
    int base = t * 10;
    int loc[10];
    int s = 0;
#pragma unroll
    for (int i = 0; i < 10; i++) {
        int idx = base + i;
        int c = (idx < N_ATOMS) ? g_counts[idx] : 0;
        loc[i] = s;
        s += c;
    }
    int v = s;
#pragma unroll
    for (int o = 1; o < 32; o <<= 1) {
        int u = __shfl_up_sync(0xffffffffu, v, o);
        if (lane >= o) v += u;
    }
    if (lane == 31) wsum[wid] = v;
    __syncthreads();
    if (wid == 0) {
        int x = wsum[lane];
#pragma unroll
        for (int o = 1; o < 32; o <<= 1) {
            int u = __shfl_up_sync(0xffffffffu, x, o);
            if (lane >= o) x += u;
        }
        wsum[lane] = x;
    }
    __syncthreads();
    int wbase = (wid > 0) ? wsum[wid - 1] : 0;
    int excl = wbase + v - s;
#pragma unroll
    for (int i = 0; i < 10; i++) {
        int idx = base + i;
        if (idx < N_ATOMS) {
            int o = excl + loc[i];
            g_offsets[idx] = o;
            g_cursor[idx]  = o;
            g_counts[idx]  = 0;
        }
    }
    if (t == 1023) g_offsets[N_ATOMS] = wbase + v;
}

// ---------------- K_prep: scatter + geometry + rbf (slot-ordered) ----------
__global__ void __launch_bounds__(256) k_prep(
    const int* __restrict__ src, const int* __restrict__ pdst,
    const int* __restrict__ anum,
    const float* __restrict__ dij, const float* __restrict__ rij) {
    int i = blockIdx.x * 256 + threadIdx.x;
    int lane = threadIdx.x & 31;
    if ((i & ~31) >= N_PAIRS) return;

    float d = dij[i];
    float rc = (d < 0.5f) ? 0.5f * (__cosf(6.2831853071795865f * d) + 1.0f) : 0.0f;
    int zd = anum[pdst[i]];

    float rx = rij[3 * i], ry = rij[3 * i + 1], rz = rij[3 * i + 2];
    float inv = 1.0f / d;
    float ux = rx * inv, uy = ry * inv, uz = rz * inv;
    float tr3 = (ux * ux + uy * uy + uz * uz) * (1.0f / 3.0f);
    float ee = __expf(-RBF_ALPHA * d);

    int pos = atomicAdd(&g_cursor[src[i]], 1);
    g_geoA[pos] = make_float4(ux, uy, uz, rc);
    g_geoB[pos] = make_float4(ux * ux - tr3, uy * uy - tr3, uz * uz - tr3,
                              __int_as_float(zd));
    g_geoC[pos] = make_float4(ux * uy, ux * uz, uy * uz, 0.0f);

    const float rbf_step = (1.0f - RBF_START) * (1.0f / 31.0f);
    float tb = (1.0f - RBF_START) * (2.0f / 32.0f);
    const float beta = 1.0f / (tb * tb);
    const float mlane = RBF_START + rbf_step * (float)lane;
#pragma unroll 4
    for (int j = 0; j < 32; j++) {
        float ee_b  = __shfl_sync(0xffffffffu, ee,  j);
        float rc_b  = __shfl_sync(0xffffffffu, rc,  j);
        int   pos_b = __shfl_sync(0xffffffffu, pos, j);
        float dfm = ee_b - mlane;
        g_rbf[pos_b * 32 + lane] = __expf(-beta * dfm * dfm) * rc_b;
    }
}

// ---------------- K_pairs (launch #4 -> gets profiled) ----------------
__global__ void __launch_bounds__(256) k_pairs(
    const int* __restrict__ anum,
    const float* __restrict__ dp1w, const float* __restrict__ dp2w,
    const float* __restrict__ dp3w,
    const float* __restrict__ dp1b, const float* __restrict__ dp2b,
    const float* __restrict__ dp3b,
    const float* __restrict__ lng, const float* __restrict__ lnb) {
    __shared__ __align__(16) ulonglong2 sh_dp12[R * 32]; // (w1 pair, w2 pair) pre-packed
    __shared__ __align__(16) ull        sh_dp3[R * 32];  // w3 pair
    __shared__ __align__(16) float4     sh_rbf[8][R];

    for (int e = threadIdx.x; e < R * 32; e += 256) {
        int r = e >> 5, l = e & 31;
        int h0 = 2 * l, h1 = 2 * l + 1;
        sh_dp12[e] = make_ulonglong2(pk2(dp1w[h0 * R + r], dp1w[h1 * R + r]),
                                     pk2(dp2w[h0 * R + r], dp2w[h1 * R + r]));
        sh_dp3[e]  = pk2(dp3w[h0 * R + r], dp3w[h1 * R + r]);
    }
    __syncthreads();

    int w    = threadIdx.x >> 5;
    int lane = threadIdx.x & 31;
    int a    = blockIdx.x * 8 + w;

    int start = g_offsets[a];
    int end   = g_offsets[a + 1];
    int za    = anum[a];

    const float2* U2 = reinterpret_cast<const float2*>(g_U);
    const float2* V2 = reinterpret_cast<const float2*>(g_V);
    float2 ubv = U2[za * 32 + lane];
    float2 b1v = reinterpret_cast<const float2*>(dp1b)[lane];
    float2 b2v = reinterpret_cast<const float2*>(dp2b)[lane];
    float2 b3v = reinterpret_cast<const float2*>(dp3b)[lane];
    ull b1p = pk2(b1v.x, b1v.y);
    ull b2p = pk2(b2v.x, b2v.y);
    ull b3p = pk2(b3v.x, b3v.y);
    const ull tenp = dup2(10.0f);
    const ull hunp = dup2(100.0f);

    ull cI = 0, wx = 0, wy = 0, wz = 0;
    ull sxx = 0, syy = 0, szz = 0, sxy = 0, sxz = 0, syz = 0;

    for (int it = start; it < end; it += 4) {
        float rbv[4];
#pragma unroll
        for (int pi = 0; pi < 4; pi++) {
            int idx = it + pi;
            rbv[pi] = (idx < end) ? g_rbf[idx * 32 + lane] : 0.0f;
        }
        __syncwarp();
        sh_rbf[w][lane] = make_float4(rbv[0], rbv[1], rbv[2], rbv[3]);
        __syncwarp();

        ull g1[4] = {0, 0, 0, 0}, g2[4] = {0, 0, 0, 0}, g3[4] = {0, 0, 0, 0};
#pragma unroll
        for (int r = 0; r < R; r++) {
            ulonglong2 w12 = sh_dp12[r * 32 + lane];
            ull w3p = sh_dp3[r * 32 + lane];
            float4 rq = sh_rbf[w][r];
            ull r0 = dup2(rq.x), r1 = dup2(rq.y), r2 = dup2(rq.z), r3 = dup2(rq.w);
            g1[0] = fma2_(r0, w12.x, g1[0]); g2[0] = fma2_(r0, w12.y, g2[0]); g3[0] = fma2_(r0, w3p, g3[0]);
            g1[1] = fma2_(r1, w12.x, g1[1]); g2[1] = fma2_(r1, w12.y, g2[1]); g3[1] = fma2_(r1, w3p, g3[1]);
            g1[2] = fma2_(r2, w12.x, g1[2]); g2[2] = fma2_(r2, w12.y, g2[2]); g3[2] = fma2_(r2, w3p, g3[2]);
            g1[3] = fma2_(r3, w12.x, g1[3]); g2[3] = fma2_(r3, w12.y, g2[3]); g3[3] = fma2_(r3, w3p, g3[3]);
        }
        __syncwarp();

#pragma unroll
        for (int pi = 0; pi < 4; pi++) {
            int idx = it + pi;
            if (idx < end) {
                float4 gA = g_geoA[idx];
                float4 gB = g_geoB[idx];
                float4 gC = g_geoC[idx];
                int zd = __float_as_int(gB.w);
                float2 vb = V2[zd * 32 + lane];
                float rc = gA.w;
                ull Cp = pk2(rc * (ubv.x + vb.x), rc * (ubv.y + vb.y));
                ull f1 = mul2_(add2_(g1[pi], b1p), Cp);
                ull f2 = mul2_(mul2_(add2_(g2[pi], b2p), Cp), tenp);
                ull f3 = mul2_(mul2_(add2_(g3[pi], b3p), Cp), hunp);
                cI  = add2_(cI, f1);
                wx  = fma2_(f2, dup2(gA.x), wx);
                wy  = fma2_(f2, dup2(gA.y), wy);
                wz  = fma2_(f2, dup2(gA.z), wz);
                sxx = fma2_(f3, dup2(gB.x), sxx);
                syy = fma2_(f3, dup2(gB.y), syy);
                szz = fma2_(f3, dup2(gB.z), szz);
                sxy = fma2_(f3, dup2(gC.x), sxy);
                sxz = fma2_(f3, dup2(gC.y), sxz);
                syz = fma2_(f3, dup2(gC.z), syz);
            }
        }
    }

    float2 cIf = up2(cI),  wxf = up2(wx),  wyf = up2(wy),  wzf = up2(wz);
    float2 sxxf = up2(sxx), syyf = up2(syy), szzf = up2(szz);
    float2 sxyf = up2(sxy), sxzf = up2(sxz), syzf = up2(syz);

    float tA0 = cIf.x + sxxf.x, tB0 = cIf.x + syyf.x, tC0 = cIf.x + szzf.x;
    float tn0 = tA0*tA0 + tB0*tB0 + tC0*tC0
              + 2.0f * (sxyf.x*sxyf.x + wzf.x*wzf.x + sxzf.x*sxzf.x
                      + wyf.x*wyf.x + syzf.x*syzf.x + wxf.x*wxf.x);
    float tA1 = cIf.y + sxxf.y, tB1 = cIf.y + syyf.y, tC1 = cIf.y + szzf.y;
    float tn1 = tA1*tA1 + tB1*tB1 + tC1*tC1
              + 2.0f * (sxyf.y*sxyf.y + wzf.y*wzf.y + sxzf.y*sxzf.y
                      + wyf.y*wyf.y + syzf.y*syzf.y + wxf.y*wxf.y);

    float ssum = tn0 + tn1;
#pragma unroll
    for (int o = 16; o; o >>= 1) ssum += __shfl_xor_sync(0xffffffffu, ssum, o);
    float mu = ssum * (1.0f / 64.0f);
    float e0 = tn0 - mu, e1 = tn1 - mu;
    float vsum = e0 * e0 + e1 * e1;
#pragma unroll
    for (int o = 16; o; o >>= 1) vsum += __shfl_xor_sync(0xffffffffu, vsum, o);
    float rstd = rsqrtf(vsum * (1.0f / 64.0f) + 1e-5f);

    float2 lg = reinterpret_cast<const float2*>(lng)[lane];
    float2 lb = reinterpret_cast<const float2*>(lnb)[lane];
    float2 nrm;
    nrm.x = e0 * rstd * lg.x + lb.x;
    nrm.y = e1 * rstd * lg.y + lb.y;
    reinterpret_cast<float2*>(g_tnorm)[a * 32 + lane] = nrm;

    int oidx = a * 32 + lane;
    reinterpret_cast<float2*>(g_comp[0])[oidx] = cIf;
    reinterpret_cast<float2*>(g_comp[1])[oidx] = wxf;
    reinterpret_cast<float2*>(g_comp[2])[oidx] = wyf;
    reinterpret_cast<float2*>(g_comp[3])[oidx] = wzf;
    reinterpret_cast<float2*>(g_comp[4])[oidx] = sxxf;
    reinterpret_cast<float2*>(g_comp[5])[oidx] = syyf;
    reinterpret_cast<float2*>(g_comp[6])[oidx] = szzf;
    reinterpret_cast<float2*>(g_comp[7])[oidx] = sxyf;
    reinterpret_cast<float2*>(g_comp[8])[oidx] = sxzf;
    reinterpret_cast<float2*>(g_comp[9])[oidx] = syzf;
}

// ---------------- K_mlpfinal: 8 atoms/block, 53.6KB smem (3 blocks/SM) --------
#define RES_C 520   // 64*8 + 8 pad
__global__ void __launch_bounds__(640) k_mlpfinal(
    const float* __restrict__ ls1w, const float* __restrict__ ls1b,
    const float* __restrict__ ls2w, const float* __restrict__ ls2b,
    float* __restrict__ out) {
    extern __shared__ float sm[];
    float* csh  = sm;                        // [(c*64+h)*8+aa]   5120
    float* res  = csh + 5120;                // [c*520 + g*8+aa]  5200
    float* nm   = res + 5200;                // [aa*192 + j]      1536
    float* nshT = nm + 1536;                 // [k*8+aa]           512
    float* h1T  = nshT + 512;                // [j*8+aa]          1024

    int tid = threadIdx.x;
    int ab  = blockIdx.x * 8;

    for (int e = tid; e < 5120; e += 640) {   // coalesced reads, strided STS
        int h = e & 63;
        int t = e >> 6;                       // c*8+aa
        int c = t >> 3, aa = t & 7;
        csh[(c * 64 + h) * 8 + aa] = g_comp[c][(ab + aa) * 64 + h];
    }
    if (tid < 512) {
        int aa = tid >> 6, k = tid & 63;
        nshT[k * 8 + aa] = g_tnorm[(ab + aa) * 64 + k];
    }
    __syncthreads();

    // ---- channel-mix GEMM: res[c][g][aa] = sum_h ltT[m][h][g] * comp[c][h][aa]
    {
        int c = tid >> 6, g = tid & 63;
        int m = (c == 0) ? 0 : (c < 4) ? 1 : 2;
        const float* wcol = g_ltT + m * 4096 + g;     // [h][g], coalesced over g
        ull acc[4] = {0, 0, 0, 0};
#pragma unroll 8
        for (int h = 0; h < 64; h++) {
            ull wd = dup2(wcol[h * 64]);
            const ulonglong2* cp =
                reinterpret_cast<const ulonglong2*>(&csh[(c * 64 + h) * 8]);
            ulonglong2 q0 = cp[0], q1 = cp[1];
            acc[0] = fma2_(wd, q0.x, acc[0]);
            acc[1] = fma2_(wd, q0.y, acc[1]);
            acc[2] = fma2_(wd, q1.x, acc[2]);
            acc[3] = fma2_(wd, q1.y, acc[3]);
        }
        ull* rp = reinterpret_cast<ull*>(&res[c * RES_C + g * 8]);
#pragma unroll
        for (int i = 0; i < 4; i++) rp[i] = acc[i];
    }
    __syncthreads();

    // ---- MLP layer 1: 64 -> 128, silu (256 threads, 4 atoms each)
    if (tid < 256) {
        int j = tid & 127, half = tid >> 7;
        ull bp = dup2(ls1b[j]);
        ull a0 = bp, a1 = bp;
        const float4* wrow = reinterpret_cast<const float4*>(ls1w + j * 64);
#pragma unroll
        for (int k4 = 0; k4 < 16; k4++) {
            float4 wv = wrow[k4];
#pragma unroll
            for (int kk = 0; kk < 4; kk++) {
                float wsc = (kk == 0) ? wv.x : (kk == 1) ? wv.y : (kk == 2) ? wv.z : wv.w;
                ull wd = dup2(wsc);
                const ull* hp = reinterpret_cast<const ull*>(&nshT[(k4 * 4 + kk) * 8 + half * 4]);
                a0 = fma2_(wd, hp[0], a0);
                a1 = fma2_(wd, hp[1], a1);
            }
        }
        float rr[4]; float2 f;
        f = up2(a0); rr[0] = f.x; rr[1] = f.y;
        f = up2(a1); rr[2] = f.x; rr[3] = f.y;
#pragma unroll
        for (int i = 0; i < 4; i++) rr[i] = rr[i] / (1.0f + __expf(-rr[i]));
        *reinterpret_cast<float4*>(&h1T[j * 8 + half * 4]) =
            make_float4(rr[0], rr[1], rr[2], rr[3]);
    }
    __syncthreads();

    // ---- MLP layer 2: 128 -> 192, silu (192 threads)
    if (tid < 192) {
        int j = tid;
        ull bp = dup2(ls2b[j]);
        ull acc[4] = {bp, bp, bp, bp};
        const float4* wrow = reinterpret_cast<const float4*>(ls2w + j * 128);
#pragma unroll 4
        for (int k4 = 0; k4 < 32; k4++) {
            float4 wv = wrow[k4];
#pragma unroll
            for (int kk = 0; kk < 4; kk++) {
                float wsc = (kk == 0) ? wv.x : (kk == 1) ? wv.y : (kk == 2) ? wv.z : wv.w;
                ull wd = dup2(wsc);
                const ull* hp = reinterpret_cast<const ull*>(&h1T[(k4 * 4 + kk) * 8]);
#pragma unroll
                for (int i = 0; i < 4; i++) acc[i] = fma2_(wd, hp[i], acc[i]);
            }
        }
#pragma unroll
        for (int i = 0; i < 4; i++) {
            float2 f = up2(acc[i]);
            nm[(2 * i)     * 192 + j] = f.x / (1.0f + __expf(-f.x));
            nm[(2 * i + 1) * 192 + j] = f.y / (1.0f + __expf(-f.y));
        }
    }
    __syncthreads();

    // ---- assemble 3x3 outputs (coalesced)
    for (int e = tid; e < 4608; e += 640) {
        int aa = e / 576;
        int rem = e - aa * 576;
        int g2 = rem / 9;
        int ij = rem - g2 * 9;
        int i3 = (ij * 11) >> 5;
        int jc = ij - i3 * 3;
        bool dg = (i3 == jc);
        int sidx = dg ? (4 + i3) : (6 + i3 + jc);
        int aidx = dg ? 1 : (4 - (i3 + jc));
        float sgn = dg ? 0.0f : ((((i3 - jc) + 3) % 3 == 1) ? 1.0f : -1.0f);
        float n0 = nm[aa * 192 + g2 * 3 + 0];
        float n1 = nm[aa * 192 + g2 * 3 + 1];
        float n2 = nm[aa * 192 + g2 * 3 + 2];
        float cIv = res[g2 * 8 + aa];
        float av  = res[aidx * RES_C + g2 * 8 + aa];
        float sv  = res[sidx * RES_C + g2 * 8 + aa];
        float iv = dg ? cIv : 0.0f;
        out[ab * 576 + e] = iv * n0 + sgn * av * n1 + sv * n2;
    }
}

// ---------------- launch ----------------
extern "C" void kernel_launch(void* const* d_in, const int* in_sizes, int n_in,
                              void* d_out, int out_size) {
    const int*   anum  = (const int*)d_in[0];
    const int*   psrc  = (const int*)d_in[1];
    const int*   pdst  = psrc + N_PAIRS;
    const float* dij   = (const float*)d_in[2];
    const float* rij   = (const float*)d_in[3];
    const float* emb   = (const float*)d_in[4];
    const float* e2w   = (const float*)d_in[5];
    const float* e2b   = (const float*)d_in[6];
    const float* dp1w  = (const float*)d_in[7];
    const float* dp1b  = (const float*)d_in[8];
    const float* dp2w  = (const float*)d_in[9];
    const float* dp2b  = (const float*)d_in[10];
    const float* dp3w  = (const float*)d_in[11];
    const float* dp3b  = (const float*)d_in[12];
    const float* lt0   = (const float*)d_in[13];
    const float* lt1   = (const float*)d_in[14];
    const float* lt2   = (const float*)d_in[15];
    const float* ls1w  = (const float*)d_in[16];
    const float* ls1b  = (const float*)d_in[17];
    const float* ls2w  = (const float*)d_in[18];
    const float* ls2b  = (const float*)d_in[19];
    const float* lng   = (const float*)d_in[20];
    const float* lnb   = (const float*)d_in[21];
    float* out = (float*)d_out;

    const size_t fused_smem = (5120 + 5200 + 1536 + 512 + 1024) * sizeof(float);
    cudaFuncSetAttribute(k_mlpfinal, cudaFuncAttributeMaxDynamicSharedMemorySize,
                         (int)fused_smem);

    k_pre<<<PRE_BLOCKS, 256>>>(psrc, emb, e2w, e2b, lt0, lt1, lt2);
    k_scan<<<1, 1024>>>();
    k_prep<<<(N_PAIRS + 255) / 256, 256>>>(psrc, pdst, anum, dij, rij);
    k_pairs<<<N_ATOMS / 8, 256>>>(anum, dp1w, dp2w, dp3w, dp1b, dp2b, dp3b, lng, lnb);
    k_mlpfinal<<<N_ATOMS / 8, 640, fused_smem>>>(ls1w, ls1b, ls2w, ls2b, out);
}

// round 6
// speedup vs baseline: 2.0875x; 1.0337x over previous
#include <cuda_runtime.h>
#include <math.h>

#define N_ATOMS 10000
#define N_PAIRS 100000
#define H 64
#define R 32
#define MAX_Z 100

typedef unsigned long long ull;

// -------- f32x2 packed math helpers (sm_10x) --------
__device__ __forceinline__ ull pk2(float x, float y) {
    ull r; asm("mov.b64 %0,{%1,%2};" : "=l"(r) : "f"(x), "f"(y)); return r;
}
__device__ __forceinline__ float2 up2(ull v) {
    float2 f; asm("mov.b64 {%0,%1},%2;" : "=f"(f.x), "=f"(f.y) : "l"(v)); return f;
}
__device__ __forceinline__ ull dup2(float x) { return pk2(x, x); }
__device__ __forceinline__ ull fma2_(ull a, ull b, ull c) {
    ull d; asm("fma.rn.f32x2 %0,%1,%2,%3;" : "=l"(d) : "l"(a), "l"(b), "l"(c)); return d;
}
__device__ __forceinline__ ull add2_(ull a, ull b) {
    ull d; asm("add.rn.f32x2 %0,%1,%2;" : "=l"(d) : "l"(a), "l"(b)); return d;
}
__device__ __forceinline__ ull mul2_(ull a, ull b) {
    ull d; asm("mul.rn.f32x2 %0,%1,%2;" : "=l"(d) : "l"(a), "l"(b)); return d;
}

// ---------------- scratch ----------------
__device__ __align__(16) float g_U[MAX_Z * H];
__device__ __align__(16) float g_V[MAX_Z * H];
__device__ __align__(16) float g_ltT[3 * H * H];    // [m][h][g]
__device__ __align__(16) float g_ls1T[64 * 128];    // [k][j]
__device__ __align__(16) float g_ls2T[128 * 192];   // [k][j]
__device__ int   g_counts[N_ATOMS];                 // zero-init; self-cleaned by k_scan
__device__ int   g_offsets[N_ATOMS + 1];
__device__ int   g_cursor[N_ATOMS];
__device__ __align__(16) float4 g_geoA[N_PAIRS];    // ux,uy,uz,rc (slot-ordered)
__device__ __align__(16) float4 g_geoB[N_PAIRS];    // txx,tyy,tzz,-
__device__ __align__(16) float4 g_geoC[N_PAIRS];    // txy,txz,tyz,-
__device__ __align__(16) ull g_f1[N_PAIRS * 32];    // f1 per (pair, h-pair)
__device__ __align__(16) ull g_f2[N_PAIRS * 32];
__device__ __align__(16) ull g_f3[N_PAIRS * 32];
__device__ __align__(16) float g_comp[10][N_ATOMS * H];
__device__ __align__(16) float g_tnorm[N_ATOMS * H];

#define RBF_START 0.60653065971263342f
#define RBF_ALPHA 10.0f

#define HIST_BLOCKS 391
#define UV_BLOCKS   25
#define LTT_BLOCKS  48
#define L1T_BLOCKS  32
#define L2T_BLOCKS  96
#define PRE_BLOCKS  (HIST_BLOCKS + UV_BLOCKS + LTT_BLOCKS + L1T_BLOCKS + L2T_BLOCKS)

// ---------------- K_pre: hist + UV + weight transposes ----------------
__global__ void __launch_bounds__(256) k_pre(
    const int* __restrict__ src,
    const float* __restrict__ emb, const float* __restrict__ w2,
    const float* __restrict__ b2,
    const float* __restrict__ lt0, const float* __restrict__ lt1,
    const float* __restrict__ lt2,
    const float* __restrict__ ls1w, const float* __restrict__ ls2w) {
    int b = blockIdx.x;
    int tid = threadIdx.x;
    if (b < HIST_BLOCKS) {
        int i = b * 256 + tid;
        if (i < N_PAIRS) atomicAdd(&g_counts[src[i]], 1);
    } else if (b < HIST_BLOCKS + UV_BLOCKS) {
        __shared__ float se[4][H];
        int ty = tid >> 6;
        int h  = tid & 63;
        int t  = (b - HIST_BLOCKS) * 4 + ty;
        se[ty][h] = emb[t * H + h];
        __syncthreads();
        float u = b2[h];
        float v = 0.0f;
        const float* wr = w2 + h * 2 * H;
#pragma unroll
        for (int k = 0; k < H; k++) {
            u += se[ty][k] * wr[k];
            v += se[ty][k] * wr[H + k];
        }
        g_U[t * H + h] = u;
        g_V[t * H + h] = v;
    } else if (b < HIST_BLOCKS + UV_BLOCKS + LTT_BLOCKS) {
        int idx = (b - HIST_BLOCKS - UV_BLOCKS) * 256 + tid;   // < 12288
        int m = idx >> 12;
        int rem = idx & 4095;
        int g = rem >> 6, h = rem & 63;
        const float* s = (m == 0) ? lt0 : (m == 1) ? lt1 : lt2;
        g_ltT[m * 4096 + h * 64 + g] = s[rem];
    } else if (b < HIST_BLOCKS + UV_BLOCKS + LTT_BLOCKS + L1T_BLOCKS) {
        int idx = (b - HIST_BLOCKS - UV_BLOCKS - LTT_BLOCKS) * 256 + tid;  // < 8192
        int k = idx >> 7, j = idx & 127;
        g_ls1T[idx] = ls1w[j * 64 + k];
    } else {
        int idx = (b - HIST_BLOCKS - UV_BLOCKS - LTT_BLOCKS - L1T_BLOCKS) * 256 + tid;
        int k = idx / 192, j = idx - k * 192;   // idx < 24576
        g_ls2T[idx] = ls2w[j * 128 + k];
    }
}

// ---------------- scan (self-cleans counts) ----------------
__global__ void k_scan() {
    __shared__ int wsum[32];
    int t = threadIdx.x;
    int lane = t & 31, wid = t >> 5;
    int base = t * 10;
    int loc[10];
    int s = 0;
#pragma unroll
    for (int i = 0; i < 10; i++) {
        int idx = base + i;
        int c = (idx < N_ATOMS) ? g_counts[idx] : 0;
        loc[i] = s;
        s += c;
    }
    int v = s;
#pragma unroll
    for (int o = 1; o < 32; o <<= 1) {
        int u = __shfl_up_sync(0xffffffffu, v, o);
        if (lane >= o) v += u;
    }
    if (lane == 31) wsum[wid] = v;
    __syncthreads();
    if (wid == 0) {
        int x = wsum[lane];
#pragma unroll
        for (int o = 1; o < 32; o <<= 1) {
            int u = __shfl_up_sync(0xffffffffu, x, o);
            if (lane >= o) x += u;
        }
        wsum[lane] = x;
    }
    __syncthreads();
    int wbase = (wid > 0) ? wsum[wid - 1] : 0;
    int excl = wbase + v - s;
#pragma unroll
    for (int i = 0; i < 10; i++) {
        int idx = base + i;
        if (idx < N_ATOMS) {
            int o = excl + loc[i];
            g_offsets[idx] = o;
            g_cursor[idx]  = o;
            g_counts[idx]  = 0;
        }
    }
    if (t == 1023) g_offsets[N_ATOMS] = wbase + v;
}

// ---------------- K_prep: scatter + geometry + rbf + f1/f2/f3 GEMM ----------
#define PREP_SMEM (16384 + 8192 + 32768)
__global__ void __launch_bounds__(256) k_prep(
    const int* __restrict__ src, const int* __restrict__ pdst,
    const int* __restrict__ anum,
    const float* __restrict__ dij, const float* __restrict__ rij,
    const float* __restrict__ dp1w, const float* __restrict__ dp2w,
    const float* __restrict__ dp3w,
    const float* __restrict__ dp1b, const float* __restrict__ dp2b,
    const float* __restrict__ dp3b) {
    extern __shared__ char smraw[];
    ulonglong2* sh_dp12 = reinterpret_cast<ulonglong2*>(smraw);          // [r*32+lane]
    ull*        sh_dp3  = reinterpret_cast<ull*>(smraw + 16384);
    float*      s_rbf   = reinterpret_cast<float*>(smraw + 24576);      // [w][p][r]

    int tid = threadIdx.x;
    for (int e = tid; e < R * 32; e += 256) {
        int r = e >> 5, l = e & 31;
        int h0 = 2 * l, h1 = h0 + 1;
        sh_dp12[e] = make_ulonglong2(pk2(dp1w[h0 * R + r], dp1w[h1 * R + r]),
                                     pk2(dp2w[h0 * R + r], dp2w[h1 * R + r]));
        sh_dp3[e]  = pk2(dp3w[h0 * R + r], dp3w[h1 * R + r]);
    }
    __syncthreads();

    int w = tid >> 5, lane = tid & 31;
    int i = blockIdx.x * 256 + tid;
    if ((i & ~31) >= N_PAIRS) return;     // whole warps only (N_PAIRS % 32 == 0)

    // stage 1: geometry + scatter
    float d = dij[i];
    float rc = (d < 0.5f) ? 0.5f * (__cosf(6.2831853071795865f * d) + 1.0f) : 0.0f;
    int za = anum[src[i]];
    int zd = anum[pdst[i]];
    float rx = rij[3 * i], ry = rij[3 * i + 1], rz = rij[3 * i + 2];
    float inv = 1.0f / d;
    float ux = rx * inv, uy = ry * inv, uz = rz * inv;
    float tr3 = (ux * ux + uy * uy + uz * uz) * (1.0f / 3.0f);
    float ee = __expf(-RBF_ALPHA * d);
    int pos = atomicAdd(&g_cursor[src[i]], 1);
    g_geoA[pos] = make_float4(ux, uy, uz, rc);
    g_geoB[pos] = make_float4(ux * ux - tr3, uy * uy - tr3, uz * uz - tr3, 0.0f);
    g_geoC[pos] = make_float4(ux * uy, ux * uz, uy * uz, 0.0f);

    // stage 2: warp-cooperative rbf -> smem [p][r]
    const float rbf_step = (1.0f - RBF_START) * (1.0f / 31.0f);
    float tb = (1.0f - RBF_START) * (2.0f / 32.0f);
    const float beta = 1.0f / (tb * tb);
    const float mlane = RBF_START + rbf_step * (float)lane;
    float* myrbf = s_rbf + w * 1024;
#pragma unroll 4
    for (int j = 0; j < 32; j++) {
        float ee_b = __shfl_sync(0xffffffffu, ee, j);
        float rc_b = __shfl_sync(0xffffffffu, rc, j);
        float dfm = ee_b - mlane;
        myrbf[j * 32 + lane] = __expf(-beta * dfm * dfm) * rc_b;
    }
    __syncwarp();

    float2 b1v = reinterpret_cast<const float2*>(dp1b)[lane];
    float2 b2v = reinterpret_cast<const float2*>(dp2b)[lane];
    float2 b3v = reinterpret_cast<const float2*>(dp3b)[lane];
    ull b1p = pk2(b1v.x, b1v.y);
    ull b2p = pk2(b2v.x, b2v.y);
    ull b3p = pk2(b3v.x, b3v.y);
    const ull tenp = dup2(10.0f);
    const ull hunp = dup2(100.0f);
    const float2* U2 = reinterpret_cast<const float2*>(g_U);
    const float2* V2 = reinterpret_cast<const float2*>(g_V);

    // stage 3: rbf @ W, fold C, write f1/f2/f3 (8 pairs per group, all full)
#pragma unroll 1
    for (int grp = 0; grp < 4; grp++) {
        ull g1[8] = {0,0,0,0,0,0,0,0};
        ull g2[8] = {0,0,0,0,0,0,0,0};
        ull g3[8] = {0,0,0,0,0,0,0,0};
        const float* rb = myrbf + grp * 8 * 32;
#pragma unroll
        for (int r = 0; r < R; r++) {
            ulonglong2 w12 = sh_dp12[r * 32 + lane];
            ull w3 = sh_dp3[r * 32 + lane];
#pragma unroll
            for (int pi = 0; pi < 8; pi++) {
                ull rv = dup2(rb[pi * 32 + r]);
                g1[pi] = fma2_(rv, w12.x, g1[pi]);
                g2[pi] = fma2_(rv, w12.y, g2[pi]);
                g3[pi] = fma2_(rv, w3,    g3[pi]);
            }
        }
#pragma unroll
        for (int pi = 0; pi < 8; pi++) {
            int p = grp * 8 + pi;
            int   pos_b = __shfl_sync(0xffffffffu, pos, p);
            int   za_b  = __shfl_sync(0xffffffffu, za,  p);
            int   zd_b  = __shfl_sync(0xffffffffu, zd,  p);
            float rc_b  = __shfl_sync(0xffffffffu, rc,  p);
            float2 ubv = U2[za_b * 32 + lane];
            float2 vbv = V2[zd_b * 32 + lane];
            ull Cp = pk2(rc_b * (ubv.x + vbv.x), rc_b * (ubv.y + vbv.y));
            g_f1[pos_b * 32 + lane] = mul2_(add2_(g1[pi], b1p), Cp);
            g_f2[pos_b * 32 + lane] = mul2_(mul2_(add2_(g2[pi], b2p), Cp), tenp);
            g_f3[pos_b * 32 + lane] = mul2_(mul2_(add2_(g3[pi], b3p), Cp), hunp);
        }
    }
}

// ---------------- K_pairs: pure streaming accumulate + layernorm ----------------
__global__ void __launch_bounds__(256) k_pairs(
    const float* __restrict__ lng, const float* __restrict__ lnb) {
    int w    = threadIdx.x >> 5;
    int lane = threadIdx.x & 31;
    int a    = blockIdx.x * 8 + w;

    int start = g_offsets[a];
    int end   = g_offsets[a + 1];

    ull cI = 0, wx = 0, wy = 0, wz = 0;
    ull sxx = 0, syy = 0, szz = 0, sxy = 0, sxz = 0, syz = 0;

#pragma unroll 2
    for (int idx = start; idx < end; idx++) {
        ull f1 = g_f1[idx * 32 + lane];
        ull f2 = g_f2[idx * 32 + lane];
        ull f3 = g_f3[idx * 32 + lane];
        float4 gA = g_geoA[idx];
        float4 gB = g_geoB[idx];
        float4 gC = g_geoC[idx];
        cI  = add2_(cI, f1);
        wx  = fma2_(f2, dup2(gA.x), wx);
        wy  = fma2_(f2, dup2(gA.y), wy);
        wz  = fma2_(f2, dup2(gA.z), wz);
        sxx = fma2_(f3, dup2(gB.x), sxx);
        syy = fma2_(f3, dup2(gB.y), syy);
        szz = fma2_(f3, dup2(gB.z), szz);
        sxy = fma2_(f3, dup2(gC.x), sxy);
        sxz = fma2_(f3, dup2(gC.y), sxz);
        syz = fma2_(f3, dup2(gC.z), syz);
    }

    float2 cIf = up2(cI),  wxf = up2(wx),  wyf = up2(wy),  wzf = up2(wz);
    float2 sxxf = up2(sxx), syyf = up2(syy), szzf = up2(szz);
    float2 sxyf = up2(sxy), sxzf = up2(sxz), syzf = up2(syz);

    float tA0 = cIf.x + sxxf.x, tB0 = cIf.x + syyf.x, tC0 = cIf.x + szzf.x;
    float tn0 = tA0*tA0 + tB0*tB0 + tC0*tC0
              + 2.0f * (sxyf.x*sxyf.x + wzf.x*wzf.x + sxzf.x*sxzf.x
                      + wyf.x*wyf.x + syzf.x*syzf.x + wxf.x*wxf.x);
    float tA1 = cIf.y + sxxf.y, tB1 = cIf.y + syyf.y, tC1 = cIf.y + szzf.y;
    float tn1 = tA1*tA1 + tB1*tB1 + tC1*tC1
              + 2.0f * (sxyf.y*sxyf.y + wzf.y*wzf.y + sxzf.y*sxzf.y
                      + wyf.y*wyf.y + syzf.y*syzf.y + wxf.y*wxf.y);

    float ssum = tn0 + tn1;
#pragma unroll
    for (int o = 16; o; o >>= 1) ssum += __shfl_xor_sync(0xffffffffu, ssum, o);
    float mu = ssum * (1.0f / 64.0f);
    float e0 = tn0 - mu, e1 = tn1 - mu;
    float vsum = e0 * e0 + e1 * e1;
#pragma unroll
    for (int o = 16; o; o >>= 1) vsum += __shfl_xor_sync(0xffffffffu, vsum, o);
    float rstd = rsqrtf(vsum * (1.0f / 64.0f) + 1e-5f);

    float2 lg = reinterpret_cast<const float2*>(lng)[lane];
    float2 lb = reinterpret_cast<const float2*>(lnb)[lane];
    float2 nrm;
    nrm.x = e0 * rstd * lg.x + lb.x;
    nrm.y = e1 * rstd * lg.y + lb.y;
    reinterpret_cast<float2*>(g_tnorm)[a * 32 + lane] = nrm;

    int oidx = a * 32 + lane;
    reinterpret_cast<float2*>(g_comp[0])[oidx] = cIf;
    reinterpret_cast<float2*>(g_comp[1])[oidx] = wxf;
    reinterpret_cast<float2*>(g_comp[2])[oidx] = wyf;
    reinterpret_cast<float2*>(g_comp[3])[oidx] = wzf;
    reinterpret_cast<float2*>(g_comp[4])[oidx] = sxxf;
    reinterpret_cast<float2*>(g_comp[5])[oidx] = syyf;
    reinterpret_cast<float2*>(g_comp[6])[oidx] = szzf;
    reinterpret_cast<float2*>(g_comp[7])[oidx] = sxyf;
    reinterpret_cast<float2*>(g_comp[8])[oidx] = sxzf;
    reinterpret_cast<float2*>(g_comp[9])[oidx] = syzf;
}

// ---------------- K_mlpfinal: broadcast-LDS + coalesced-LDG design ----------
// 8 atoms/block, 256 threads. All smem scalars warp-uniform (broadcast).
#define MLPF_SMEM (5888 * 8 + 1536 * 4)
__global__ void __launch_bounds__(256) k_mlpfinal(
    const float* __restrict__ ls1b, const float* __restrict__ ls2b,
    float* __restrict__ out) {
    extern __shared__ char smraw[];
    ull*   csh  = reinterpret_cast<ull*>(smraw);       // [h*40 + ap*10 + c]  2560
    ull*   resu = csh + 2560;                          // [c*256 + g*4 + ap]  2560
    ull*   nshT = resu + 2560;                         // [k*4 + ap]           256
    ull*   h1T  = nshT + 256;                          // [j*4 + ap]           512
    float* nm   = reinterpret_cast<float*>(h1T + 512); // [aa*192 + j]        1536
    float* cshf = reinterpret_cast<float*>(csh);
    float* resf = reinterpret_cast<float*>(resu);

    int tid = threadIdx.x;
    int ab  = blockIdx.x * 8;

#pragma unroll
    for (int e0 = 0; e0 < 2560; e0 += 256) {
        int e = e0 + tid;
        int c = e >> 8, aa = (e >> 5) & 7, h2 = e & 31;
        float2 v = reinterpret_cast<const float2*>(g_comp[c])[(ab + aa) * 32 + h2];
        int ap = aa >> 1, sub = aa & 1;
        cshf[((2 * h2)     * 40 + ap * 10 + c) * 2 + sub] = v.x;
        cshf[((2 * h2 + 1) * 40 + ap * 10 + c) * 2 + sub] = v.y;
    }
    {
        int k = tid & 63, ap = tid >> 6;
        nshT[k * 4 + ap] = pk2(g_tnorm[(ab + 2 * ap) * 64 + k],
                               g_tnorm[(ab + 2 * ap + 1) * 64 + k]);
    }
    __syncthreads();

    // ---- channel-mix GEMM
    {
        int ap = tid >> 6, g = tid & 63;
        ull acc[10];
#pragma unroll
        for (int c = 0; c < 10; c++) acc[c] = 0ull;
        const float* w0p = g_ltT + g;
#pragma unroll 4
        for (int h = 0; h < 64; h++) {
            ull wd0 = dup2(w0p[h * 64]);
            ull wd1 = dup2(w0p[4096 + h * 64]);
            ull wd2 = dup2(w0p[8192 + h * 64]);
            const ulonglong2* q = reinterpret_cast<const ulonglong2*>(csh + h * 40 + ap * 10);
            ulonglong2 q0 = q[0], q1 = q[1], q2 = q[2], q3 = q[3], q4 = q[4];
            acc[0] = fma2_(wd0, q0.x, acc[0]);
            acc[1] = fma2_(wd1, q0.y, acc[1]);
            acc[2] = fma2_(wd1, q1.x, acc[2]);
            acc[3] = fma2_(wd1, q1.y, acc[3]);
            acc[4] = fma2_(wd2, q2.x, acc[4]);
            acc[5] = fma2_(wd2, q2.y, acc[5]);
            acc[6] = fma2_(wd2, q3.x, acc[6]);
            acc[7] = fma2_(wd2, q3.y, acc[7]);
            acc[8] = fma2_(wd2, q4.x, acc[8]);
            acc[9] = fma2_(wd2, q4.y, acc[9]);
        }
#pragma unroll
        for (int c = 0; c < 10; c++) resu[c * 256 + g * 4 + ap] = acc[c];
    }
    __syncthreads();

    // ---- MLP layer 1: 64 -> 128, silu (all 256 threads)
    {
        int j = tid & 127, half = tid >> 7;
        ull bp = dup2(ls1b[j]);
        ull a0 = bp, a1 = bp;
        const float* wcol = g_ls1T + j;
#pragma unroll 8
        for (int k = 0; k < 64; k++) {
            ull wd = dup2(wcol[k * 128]);
            ulonglong2 hq = *reinterpret_cast<const ulonglong2*>(nshT + k * 4 + half * 2);
            a0 = fma2_(wd, hq.x, a0);
            a1 = fma2_(wd, hq.y, a1);
        }
        float2 f0 = up2(a0), f1v = up2(a1);
        float r0 = f0.x  / (1.0f + __expf(-f0.x));
        float r1 = f0.y  / (1.0f + __expf(-f0.y));
        float r2 = f1v.x / (1.0f + __expf(-f1v.x));
        float r3 = f1v.y / (1.0f + __expf(-f1v.y));
        *reinterpret_cast<ulonglong2*>(h1T + j * 4 + half * 2) =
            make_ulonglong2(pk2(r0, r1), pk2(r2, r3));
    }
    __syncthreads();

    // ---- MLP layer 2: 128 -> 192, silu (192 threads)
    if (tid < 192) {
        int j = tid;
        ull bp = dup2(ls2b[j]);
        ull acc2[4] = {bp, bp, bp, bp};
        const float* wcol = g_ls2T + j;
#pragma unroll 4
        for (int k = 0; k < 128; k++) {
            ull wd = dup2(wcol[k * 192]);
            const ulonglong2* hq = reinterpret_cast<const ulonglong2*>(h1T + k * 4);
            ulonglong2 h0 = hq[0], h1v = hq[1];
            acc2[0] = fma2_(wd, h0.x,  acc2[0]);
            acc2[1] = fma2_(wd, h0.y,  acc2[1]);
            acc2[2] = fma2_(wd, h1v.x, acc2[2]);
            acc2[3] = fma2_(wd, h1v.y, acc2[3]);
        }
#pragma unroll
        for (int i2 = 0; i2 < 4; i2++) {
            float2 f = up2(acc2[i2]);
            nm[(2 * i2)     * 192 + j] = f.x / (1.0f + __expf(-f.x));
            nm[(2 * i2 + 1) * 192 + j] = f.y / (1.0f + __expf(-f.y));
        }
    }
    __syncthreads();

    // ---- assemble 3x3 outputs (coalesced)
#pragma unroll
    for (int e0 = 0; e0 < 4608; e0 += 256) {
        int e = e0 + tid;
        int aa = e / 576;
        int rem = e - aa * 576;
        int g2 = rem / 9;
        int ij = rem - g2 * 9;
        int i3 = (ij * 11) >> 5;
        int jc = ij - i3 * 3;
        bool dg = (i3 == jc);
        int sidx = dg ? (4 + i3) : (6 + i3 + jc);
        int aidx = dg ? 1 : (4 - (i3 + jc));
        float sgn = dg ? 0.0f : ((((i3 - jc) + 3) % 3 == 1) ? 1.0f : -1.0f);
        float n0 = nm[aa * 192 + g2 * 3 + 0];
        float n1 = nm[aa * 192 + g2 * 3 + 1];
        float n2 = nm[aa * 192 + g2 * 3 + 2];
        float cIv = resf[g2 * 8 + aa];
        float av  = resf[aidx * 512 + g2 * 8 + aa];
        float sv  = resf[sidx * 512 + g2 * 8 + aa];
        float iv = dg ? cIv : 0.0f;
        out[ab * 576 + e] = iv * n0 + sgn * av * n1 + sv * n2;
    }
}

// ---------------- launch ----------------
extern "C" void kernel_launch(void* const* d_in, const int* in_sizes, int n_in,
                              void* d_out, int out_size) {
    const int*   anum  = (const int*)d_in[0];
    const int*   psrc  = (const int*)d_in[1];
    const int*   pdst  = psrc + N_PAIRS;
    const float* dij   = (const float*)d_in[2];
    const float* rij   = (const float*)d_in[3];
    const float* emb   = (const float*)d_in[4];
    const float* e2w   = (const float*)d_in[5];
    const float* e2b   = (const float*)d_in[6];
    const float* dp1w  = (const float*)d_in[7];
    const float* dp1b  = (const float*)d_in[8];
    const float* dp2w  = (const float*)d_in[9];
    const float* dp2b  = (const float*)d_in[10];
    const float* dp3w  = (const float*)d_in[11];
    const float* dp3b  = (const float*)d_in[12];
    const float* lt0   = (const float*)d_in[13];
    const float* lt1   = (const float*)d_in[14];
    const float* lt2   = (const float*)d_in[15];
    const float* ls1w  = (const float*)d_in[16];
    const float* ls1b  = (const float*)d_in[17];
    const float* ls2w  = (const float*)d_in[18];
    const float* ls2b  = (const float*)d_in[19];
    const float* lng   = (const float*)d_in[20];
    const float* lnb   = (const float*)d_in[21];
    float* out = (float*)d_out;

    cudaFuncSetAttribute(k_prep, cudaFuncAttributeMaxDynamicSharedMemorySize, PREP_SMEM);
    cudaFuncSetAttribute(k_mlpfinal, cudaFuncAttributeMaxDynamicSharedMemorySize, MLPF_SMEM);

    k_pre<<<PRE_BLOCKS, 256>>>(psrc, emb, e2w, e2b, lt0, lt1, lt2, ls1w, ls2w);
    k_scan<<<1, 1024>>>();
    k_prep<<<(N_PAIRS + 255) / 256, 256, PREP_SMEM>>>(psrc, pdst, anum, dij, rij,
                                                      dp1w, dp2w, dp3w,
                                                      dp1b, dp2b, dp3b);
    k_pairs<<<N_ATOMS / 8, 256>>>(lng, lnb);
    k_mlpfinal<<<N_ATOMS / 8, 256, MLPF_SMEM>>>(ls1b, ls2b, out);
}

// round 8
// speedup vs baseline: 2.1058x; 1.0088x over previous
#include <cuda_runtime.h>
#include <math.h>

#define N_ATOMS 10000
#define N_PAIRS 100000
#define H 64
#define R 32
#define MAX_Z 100

typedef unsigned long long ull;

// -------- f32x2 packed math helpers (sm_10x) --------
__device__ __forceinline__ ull pk2(float x, float y) {
    ull r; asm("mov.b64 %0,{%1,%2};" : "=l"(r) : "f"(x), "f"(y)); return r;
}
__device__ __forceinline__ float2 up2(ull v) {
    float2 f; asm("mov.b64 {%0,%1},%2;" : "=f"(f.x), "=f"(f.y) : "l"(v)); return f;
}
__device__ __forceinline__ ull dup2(float x) { return pk2(x, x); }
__device__ __forceinline__ ull fma2_(ull a, ull b, ull c) {
    ull d; asm("fma.rn.f32x2 %0,%1,%2,%3;" : "=l"(d) : "l"(a), "l"(b), "l"(c)); return d;
}
__device__ __forceinline__ ull add2_(ull a, ull b) {
    ull d; asm("add.rn.f32x2 %0,%1,%2;" : "=l"(d) : "l"(a), "l"(b)); return d;
}
__device__ __forceinline__ ull mul2_(ull a, ull b) {
    ull d; asm("mul.rn.f32x2 %0,%1,%2;" : "=l"(d) : "l"(a), "l"(b)); return d;
}

// ---------------- scratch ----------------
__device__ __align__(16) float g_U[MAX_Z * H];
__device__ __align__(16) float g_V[MAX_Z * H];
__device__ __align__(16) float g_ltT[3 * H * H];    // [m][h][g]
__device__ __align__(16) float g_ls1T[64 * 128];    // [k][j]
__device__ __align__(16) float g_ls2T[128 * 192];   // [k][j]
__device__ int   g_counts[N_ATOMS];                 // zero-init; self-cleaned
__device__ int   g_offsets[N_ATOMS + 1];
__device__ int   g_cursor[N_ATOMS];
__device__ unsigned int g_ticket;                   // zero-init; self-cleaned
__device__ __align__(16) float4 g_geoA[N_PAIRS];    // ux,uy,uz,rc (slot-ordered)
__device__ __align__(16) float4 g_geoB[N_PAIRS];    // txx,tyy,tzz,-
__device__ __align__(16) float4 g_geoC[N_PAIRS];    // txy,txz,tyz,-
__device__ __align__(16) ull g_f1[N_PAIRS * 32];    // f1 per (pair, h-pair)
__device__ __align__(16) ull g_f2[N_PAIRS * 32];
__device__ __align__(16) ull g_f3[N_PAIRS * 32];
__device__ __align__(16) float g_comp[10][N_ATOMS * H];
__device__ __align__(16) float g_tnorm[N_ATOMS * H];

#define RBF_START 0.60653065971263342f
#define RBF_ALPHA 10.0f

#define HIST_BLOCKS 391
#define UV_BLOCKS   25
#define LTT_BLOCKS  48
#define L1T_BLOCKS  32
#define L2T_BLOCKS  96
#define PRE_BLOCKS  (HIST_BLOCKS + UV_BLOCKS + LTT_BLOCKS + L1T_BLOCKS + L2T_BLOCKS)

// ---------------- K_pre: hist + UV + transposes, then LAST BLOCK runs the scan --
__global__ void __launch_bounds__(256) k_pre(
    const int* __restrict__ src,
    const float* __restrict__ emb, const float* __restrict__ w2,
    const float* __restrict__ b2,
    const float* __restrict__ lt0, const float* __restrict__ lt1,
    const float* __restrict__ lt2,
    const float* __restrict__ ls1w, const float* __restrict__ ls2w) {
    int b = blockIdx.x;
    int tid = threadIdx.x;
    if (b < HIST_BLOCKS) {
        int i = b * 256 + tid;
        if (i < N_PAIRS) atomicAdd(&g_counts[src[i]], 1);
    } else if (b < HIST_BLOCKS + UV_BLOCKS) {
        __shared__ float se[4][H];
        int ty = tid >> 6;
        int h  = tid & 63;
        int t  = (b - HIST_BLOCKS) * 4 + ty;
        se[ty][h] = emb[t * H + h];
        __syncthreads();
        float u = b2[h];
        float v = 0.0f;
        const float* wr = w2 + h * 2 * H;
#pragma unroll
        for (int k = 0; k < H; k++) {
            u += se[ty][k] * wr[k];
            v += se[ty][k] * wr[H + k];
        }
        g_U[t * H + h] = u;
        g_V[t * H + h] = v;
    } else if (b < HIST_BLOCKS + UV_BLOCKS + LTT_BLOCKS) {
        int idx = (b - HIST_BLOCKS - UV_BLOCKS) * 256 + tid;   // < 12288
        int m = idx >> 12;
        int rem = idx & 4095;
        int g = rem >> 6, h = rem & 63;
        const float* s = (m == 0) ? lt0 : (m == 1) ? lt1 : lt2;
        g_ltT[m * 4096 + h * 64 + g] = s[rem];
    } else if (b < HIST_BLOCKS + UV_BLOCKS + LTT_BLOCKS + L1T_BLOCKS) {
        int idx = (b - HIST_BLOCKS - UV_BLOCKS - LTT_BLOCKS) * 256 + tid;  // < 8192
        int k = idx >> 7, j = idx & 127;
        g_ls1T[idx] = ls1w[j * 64 + k];
    } else {
        int idx = (b - HIST_BLOCKS - UV_BLOCKS - LTT_BLOCKS - L1T_BLOCKS) * 256 + tid;
        int k = idx / 192, j = idx - k * 192;   // idx < 24576
        g_ls2T[idx] = ls2w[j * 128 + k];
    }

    // ---- last-block ticket: the final block to finish runs the scan ----
    __shared__ int s_last;
    __syncthreads();
    if (tid == 0) {
        __threadfence();
        unsigned int t = atomicAdd(&g_ticket, 1u);
        s_last = (t == (unsigned)(PRE_BLOCKS - 1)) ? 1 : 0;
    }
    __syncthreads();
    if (!s_last) return;
    __threadfence();   // acquire all producers' writes

    // scan of g_counts[0..9999] with 256 threads, 40 elems/thread (guarded!)
    __shared__ int wsum[8];
    {
        int lane = tid & 31, wid = tid >> 5;
        int base = tid * 40;
        int loc[40];
        int s = 0;
#pragma unroll
        for (int i = 0; i < 40; i++) {
            int idx = base + i;
            int c = (idx < N_ATOMS) ? g_counts[idx] : 0;
            loc[i] = s;
            s += c;
        }
        int v = s;
#pragma unroll
        for (int o = 1; o < 32; o <<= 1) {
            int u = __shfl_up_sync(0xffffffffu, v, o);
            if (lane >= o) v += u;
        }
        if (lane == 31) wsum[wid] = v;
        __syncthreads();
        if (wid == 0 && lane < 8) {
            int x = wsum[lane];
#pragma unroll
            for (int o = 1; o < 8; o <<= 1) {
                int u = __shfl_up_sync(0xffu, x, o);
                if (lane >= o) x += u;
            }
            wsum[lane] = x;
        }
        __syncthreads();
        int wbase = (wid > 0) ? wsum[wid - 1] : 0;
        int excl = wbase + v - s;
#pragma unroll
        for (int i = 0; i < 40; i++) {
            int idx = base + i;
            if (idx < N_ATOMS) {
                int o = excl + loc[i];
                g_offsets[idx] = o;
                g_cursor[idx]  = o;
                g_counts[idx]  = 0;   // restore invariant for next replay
            }
        }
        if (tid == 255) {
            g_offsets[N_ATOMS] = wbase + v;
            g_ticket = 0;             // restore invariant for next replay
        }
    }
}

// ---------------- K_prep: scatter + geometry + rbf + f1/f2/f3 GEMM ----------
#define PREP_SMEM (16384 + 8192 + 32768)
__global__ void __launch_bounds__(256) k_prep(
    const int* __restrict__ src, const int* __restrict__ pdst,
    const int* __restrict__ anum,
    const float* __restrict__ dij, const float* __restrict__ rij,
    const float* __restrict__ dp1w, const float* __restrict__ dp2w,
    const float* __restrict__ dp3w,
    const float* __restrict__ dp1b, const float* __restrict__ dp2b,
    const float* __restrict__ dp3b) {
    extern __shared__ char smraw[];
    ulonglong2* sh_dp12 = reinterpret_cast<ulonglong2*>(smraw);          // [r*32+lane]
    ull*        sh_dp3  = reinterpret_cast<ull*>(smraw + 16384);
    float*      s_rbf   = reinterpret_cast<float*>(smraw + 24576);      // [w][p][r]

    int tid = threadIdx.x;
    for (int e = tid; e < R * 32; e += 256) {
        int r = e >> 5, l = e & 31;
        int h0 = 2 * l, h1 = h0 + 1;
        sh_dp12[e] = make_ulonglong2(pk2(dp1w[h0 * R + r], dp1w[h1 * R + r]),
                                     pk2(dp2w[h0 * R + r], dp2w[h1 * R + r]));
        sh_dp3[e]  = pk2(dp3w[h0 * R + r], dp3w[h1 * R + r]);
    }
    __syncthreads();

    int w = tid >> 5, lane = tid & 31;
    int i = blockIdx.x * 256 + tid;
    if ((i & ~31) >= N_PAIRS) return;     // whole warps only (N_PAIRS % 32 == 0)

    // stage 1: geometry + scatter
    float d = dij[i];
    float rc = (d < 0.5f) ? 0.5f * (__cosf(6.2831853071795865f * d) + 1.0f) : 0.0f;
    int za = anum[src[i]];
    int zd = anum[pdst[i]];
    float rx = rij[3 * i], ry = rij[3 * i + 1], rz = rij[3 * i + 2];
    float inv = 1.0f / d;
    float ux = rx * inv, uy = ry * inv, uz = rz * inv;
    float tr3 = (ux * ux + uy * uy + uz * uz) * (1.0f / 3.0f);
    float ee = __expf(-RBF_ALPHA * d);
    int pos = atomicAdd(&g_cursor[src[i]], 1);
    g_geoA[pos] = make_float4(ux, uy, uz, rc);
    g_geoB[pos] = make_float4(ux * ux - tr3, uy * uy - tr3, uz * uz - tr3, 0.0f);
    g_geoC[pos] = make_float4(ux * uy, ux * uz, uy * uz, 0.0f);

    // stage 2: warp-cooperative rbf -> smem [p][r]
    const float rbf_step = (1.0f - RBF_START) * (1.0f / 31.0f);
    float tb = (1.0f - RBF_START) * (2.0f / 32.0f);
    const float beta = 1.0f / (tb * tb);
    const float mlane = RBF_START + rbf_step * (float)lane;
    float* myrbf = s_rbf + w * 1024;
#pragma unroll 4
    for (int j = 0; j < 32; j++) {
        float ee_b = __shfl_sync(0xffffffffu, ee, j);
        float rc_b = __shfl_sync(0xffffffffu, rc, j);
        float dfm = ee_b - mlane;
        myrbf[j * 32 + lane] = __expf(-beta * dfm * dfm) * rc_b;
    }
    __syncwarp();

    float2 b1v = reinterpret_cast<const float2*>(dp1b)[lane];
    float2 b2v = reinterpret_cast<const float2*>(dp2b)[lane];
    float2 b3v = reinterpret_cast<const float2*>(dp3b)[lane];
    ull b1p = pk2(b1v.x, b1v.y);
    ull b2p = pk2(b2v.x, b2v.y);
    ull b3p = pk2(b3v.x, b3v.y);
    const ull tenp = dup2(10.0f);
    const ull hunp = dup2(100.0f);
    const float2* U2 = reinterpret_cast<const float2*>(g_U);
    const float2* V2 = reinterpret_cast<const float2*>(g_V);

    // stage 3: rbf @ W, fold C, write f1/f2/f3
#pragma unroll 1
    for (int grp = 0; grp < 4; grp++) {
        ull g1[8] = {0,0,0,0,0,0,0,0};
        ull g2[8] = {0,0,0,0,0,0,0,0};
        ull g3[8] = {0,0,0,0,0,0,0,0};
        const float* rb = myrbf + grp * 8 * 32;
#pragma unroll
        for (int r = 0; r < R; r++) {
            ulonglong2 w12 = sh_dp12[r * 32 + lane];
            ull w3 = sh_dp3[r * 32 + lane];
#pragma unroll
            for (int pi = 0; pi < 8; pi++) {
                ull rv = dup2(rb[pi * 32 + r]);
                g1[pi] = fma2_(rv, w12.x, g1[pi]);
                g2[pi] = fma2_(rv, w12.y, g2[pi]);
                g3[pi] = fma2_(rv, w3,    g3[pi]);
            }
        }
#pragma unroll
        for (int pi = 0; pi < 8; pi++) {
            int p = grp * 8 + pi;
            int   pos_b = __shfl_sync(0xffffffffu, pos, p);
            int   za_b  = __shfl_sync(0xffffffffu, za,  p);
            int   zd_b  = __shfl_sync(0xffffffffu, zd,  p);
            float rc_b  = __shfl_sync(0xffffffffu, rc,  p);
            float2 ubv = U2[za_b * 32 + lane];
            float2 vbv = V2[zd_b * 32 + lane];
            ull Cp = pk2(rc_b * (ubv.x + vbv.x), rc_b * (ubv.y + vbv.y));
            g_f1[pos_b * 32 + lane] = mul2_(add2_(g1[pi], b1p), Cp);
            g_f2[pos_b * 32 + lane] = mul2_(mul2_(add2_(g2[pi], b2p), Cp), tenp);
            g_f3[pos_b * 32 + lane] = mul2_(mul2_(add2_(g3[pi], b3p), Cp), hunp);
        }
    }
}

// ---------------- K_pairs: pure streaming accumulate + layernorm ----------------
__global__ void __launch_bounds__(256) k_pairs(
    const float* __restrict__ lng, const float* __restrict__ lnb) {
    int w    = threadIdx.x >> 5;
    int lane = threadIdx.x & 31;
    int a    = blockIdx.x * 8 + w;

    int start = g_offsets[a];
    int end   = g_offsets[a + 1];

    ull cI = 0, wx = 0, wy = 0, wz = 0;
    ull sxx = 0, syy = 0, szz = 0, sxy = 0, sxz = 0, syz = 0;

#pragma unroll 2
    for (int idx = start; idx < end; idx++) {
        ull f1 = g_f1[idx * 32 + lane];
        ull f2 = g_f2[idx * 32 + lane];
        ull f3 = g_f3[idx * 32 + lane];
        float4 gA = g_geoA[idx];
        float4 gB = g_geoB[idx];
        float4 gC = g_geoC[idx];
        cI  = add2_(cI, f1);
        wx  = fma2_(f2, dup2(gA.x), wx);
        wy  = fma2_(f2, dup2(gA.y), wy);
        wz  = fma2_(f2, dup2(gA.z), wz);
        sxx = fma2_(f3, dup2(gB.x), sxx);
        syy = fma2_(f3, dup2(gB.y), syy);
        szz = fma2_(f3, dup2(gB.z), szz);
        sxy = fma2_(f3, dup2(gC.x), sxy);
        sxz = fma2_(f3, dup2(gC.y), sxz);
        syz = fma2_(f3, dup2(gC.z), syz);
    }

    float2 cIf = up2(cI),  wxf = up2(wx),  wyf = up2(wy),  wzf = up2(wz);
    float2 sxxf = up2(sxx), syyf = up2(syy), szzf = up2(szz);
    float2 sxyf = up2(sxy), sxzf = up2(sxz), syzf = up2(syz);

    float tA0 = cIf.x + sxxf.x, tB0 = cIf.x + syyf.x, tC0 = cIf.x + szzf.x;
    float tn0 = tA0*tA0 + tB0*tB0 + tC0*tC0
              + 2.0f * (sxyf.x*sxyf.x + wzf.x*wzf.x + sxzf.x*sxzf.x
                      + wyf.x*wyf.x + syzf.x*syzf.x + wxf.x*wxf.x);
    float tA1 = cIf.y + sxxf.y, tB1 = cIf.y + syyf.y, tC1 = cIf.y + szzf.y;
    float tn1 = tA1*tA1 + tB1*tB1 + tC1*tC1
              + 2.0f * (sxyf.y*sxyf.y + wzf.y*wzf.y + sxzf.y*sxzf.y
                      + wyf.y*wyf.y + syzf.y*syzf.y + wxf.y*wxf.y);

    float ssum = tn0 + tn1;
#pragma unroll
    for (int o = 16; o; o >>= 1) ssum += __shfl_xor_sync(0xffffffffu, ssum, o);
    float mu = ssum * (1.0f / 64.0f);
    float e0 = tn0 - mu, e1 = tn1 - mu;
    float vsum = e0 * e0 + e1 * e1;
#pragma unroll
    for (int o = 16; o; o >>= 1) vsum += __shfl_xor_sync(0xffffffffu, vsum, o);
    float rstd = rsqrtf(vsum * (1.0f / 64.0f) + 1e-5f);

    float2 lg = reinterpret_cast<const float2*>(lng)[lane];
    float2 lb = reinterpret_cast<const float2*>(lnb)[lane];
    float2 nrm;
    nrm.x = e0 * rstd * lg.x + lb.x;
    nrm.y = e1 * rstd * lg.y + lb.y;
    reinterpret_cast<float2*>(g_tnorm)[a * 32 + lane] = nrm;

    int oidx = a * 32 + lane;
    reinterpret_cast<float2*>(g_comp[0])[oidx] = cIf;
    reinterpret_cast<float2*>(g_comp[1])[oidx] = wxf;
    reinterpret_cast<float2*>(g_comp[2])[oidx] = wyf;
    reinterpret_cast<float2*>(g_comp[3])[oidx] = wzf;
    reinterpret_cast<float2*>(g_comp[4])[oidx] = sxxf;
    reinterpret_cast<float2*>(g_comp[5])[oidx] = syyf;
    reinterpret_cast<float2*>(g_comp[6])[oidx] = szzf;
    reinterpret_cast<float2*>(g_comp[7])[oidx] = sxyf;
    reinterpret_cast<float2*>(g_comp[8])[oidx] = sxzf;
    reinterpret_cast<float2*>(g_comp[9])[oidx] = syzf;
}

// ---------------- K_mlpfinal (launch #4 -> gets profiled) ----------
#define MLPF_SMEM (5888 * 8 + 1536 * 4)
__global__ void __launch_bounds__(256) k_mlpfinal(
    const float* __restrict__ ls1b, const float* __restrict__ ls2b,
    float* __restrict__ out) {
    extern __shared__ char smraw[];
    ull*   csh  = reinterpret_cast<ull*>(smraw);       // [h*40 + ap*10 + c]  2560
    ull*   resu = csh + 2560;                          // [c*256 + g*4 + ap]  2560
    ull*   nshT = resu + 2560;                         // [k*4 + ap]           256
    ull*   h1T  = nshT + 256;                          // [j*4 + ap]           512
    float* nm   = reinterpret_cast<float*>(h1T + 512); // [aa*192 + j]        1536
    float* cshf = reinterpret_cast<float*>(csh);
    float* resf = reinterpret_cast<float*>(resu);

    int tid = threadIdx.x;
    int ab  = blockIdx.x * 8;

#pragma unroll
    for (int e0 = 0; e0 < 2560; e0 += 256) {
        int e = e0 + tid;
        int c = e >> 8, aa = (e >> 5) & 7, h2 = e & 31;
        float2 v = reinterpret_cast<const float2*>(g_comp[c])[(ab + aa) * 32 + h2];
        int ap = aa >> 1, sub = aa & 1;
        cshf[((2 * h2)     * 40 + ap * 10 + c) * 2 + sub] = v.x;
        cshf[((2 * h2 + 1) * 40 + ap * 10 + c) * 2 + sub] = v.y;
    }
    {
        int k = tid & 63, ap = tid >> 6;
        nshT[k * 4 + ap] = pk2(g_tnorm[(ab + 2 * ap) * 64 + k],
                               g_tnorm[(ab + 2 * ap + 1) * 64 + k]);
    }
    __syncthreads();

    // ---- channel-mix GEMM
    {
        int ap = tid >> 6, g = tid & 63;
        ull acc[10];
#pragma unroll
        for (int c = 0; c < 10; c++) acc[c] = 0ull;
        const float* w0p = g_ltT + g;
#pragma unroll 4
        for (int h = 0; h < 64; h++) {
            ull wd0 = dup2(w0p[h * 64]);
            ull wd1 = dup2(w0p[4096 + h * 64]);
            ull wd2 = dup2(w0p[8192 + h * 64]);
            const ulonglong2* q = reinterpret_cast<const ulonglong2*>(csh + h * 40 + ap * 10);
            ulonglong2 q0 = q[0], q1 = q[1], q2 = q[2], q3 = q[3], q4 = q[4];
            acc[0] = fma2_(wd0, q0.x, acc[0]);
            acc[1] = fma2_(wd1, q0.y, acc[1]);
            acc[2] = fma2_(wd1, q1.x, acc[2]);
            acc[3] = fma2_(wd1, q1.y, acc[3]);
            acc[4] = fma2_(wd2, q2.x, acc[4]);
            acc[5] = fma2_(wd2, q2.y, acc[5]);
            acc[6] = fma2_(wd2, q3.x, acc[6]);
            acc[7] = fma2_(wd2, q3.y, acc[7]);
            acc[8] = fma2_(wd2, q4.x, acc[8]);
            acc[9] = fma2_(wd2, q4.y, acc[9]);
        }
#pragma unroll
        for (int c = 0; c < 10; c++) resu[c * 256 + g * 4 + ap] = acc[c];
    }
    __syncthreads();

    // ---- MLP layer 1: 64 -> 128, silu
    {
        int j = tid & 127, half = tid >> 7;
        ull bp = dup2(ls1b[j]);
        ull a0 = bp, a1 = bp;
        const float* wcol = g_ls1T + j;
#pragma unroll 8
        for (int k = 0; k < 64; k++) {
            ull wd = dup2(wcol[k * 128]);
            ulonglong2 hq = *reinterpret_cast<const ulonglong2*>(nshT + k * 4 + half * 2);
            a0 = fma2_(wd, hq.x, a0);
            a1 = fma2_(wd, hq.y, a1);
        }
        float2 f0 = up2(a0), f1v = up2(a1);
        float r0 = f0.x  / (1.0f + __expf(-f0.x));
        float r1 = f0.y  / (1.0f + __expf(-f0.y));
        float r2 = f1v.x / (1.0f + __expf(-f1v.x));
        float r3 = f1v.y / (1.0f + __expf(-f1v.y));
        *reinterpret_cast<ulonglong2*>(h1T + j * 4 + half * 2) =
            make_ulonglong2(pk2(r0, r1), pk2(r2, r3));
    }
    __syncthreads();

    // ---- MLP layer 2: 128 -> 192, silu
    if (tid < 192) {
        int j = tid;
        ull bp = dup2(ls2b[j]);
        ull acc2[4] = {bp, bp, bp, bp};
        const float* wcol = g_ls2T + j;
#pragma unroll 4
        for (int k = 0; k < 128; k++) {
            ull wd = dup2(wcol[k * 192]);
            const ulonglong2* hq = reinterpret_cast<const ulonglong2*>(h1T + k * 4);
            ulonglong2 h0 = hq[0], h1v = hq[1];
            acc2[0] = fma2_(wd, h0.x,  acc2[0]);
            acc2[1] = fma2_(wd, h0.y,  acc2[1]);
            acc2[2] = fma2_(wd, h1v.x, acc2[2]);
            acc2[3] = fma2_(wd, h1v.y, acc2[3]);
        }
#pragma unroll
        for (int i2 = 0; i2 < 4; i2++) {
            float2 f = up2(acc2[i2]);
            nm[(2 * i2)     * 192 + j] = f.x / (1.0f + __expf(-f.x));
            nm[(2 * i2 + 1) * 192 + j] = f.y / (1.0f + __expf(-f.y));
        }
    }
    __syncthreads();

    // ---- assemble 3x3 outputs (coalesced)
#pragma unroll
    for (int e0 = 0; e0 < 4608; e0 += 256) {
        int e = e0 + tid;
        int aa = e / 576;
        int rem = e - aa * 576;
        int g2 = rem / 9;
        int ij = rem - g2 * 9;
        int i3 = (ij * 11) >> 5;
        int jc = ij - i3 * 3;
        bool dg = (i3 == jc);
        int sidx = dg ? (4 + i3) : (6 + i3 + jc);
        int aidx = dg ? 1 : (4 - (i3 + jc));
        float sgn = dg ? 0.0f : ((((i3 - jc) + 3) % 3 == 1) ? 1.0f : -1.0f);
        float n0 = nm[aa * 192 + g2 * 3 + 0];
        float n1 = nm[aa * 192 + g2 * 3 + 1];
        float n2 = nm[aa * 192 + g2 * 3 + 2];
        float cIv = resf[g2 * 8 + aa];
        float av  = resf[aidx * 512 + g2 * 8 + aa];
        float sv  = resf[sidx * 512 + g2 * 8 + aa];
        float iv = dg ? cIv : 0.0f;
        out[ab * 576 + e] = iv * n0 + sgn * av * n1 + sv * n2;
    }
}

// ---------------- launch ----------------
extern "C" void kernel_launch(void* const* d_in, const int* in_sizes, int n_in,
                              void* d_out, int out_size) {
    const int*   anum  = (const int*)d_in[0];
    const int*   psrc  = (const int*)d_in[1];
    const int*   pdst  = psrc + N_PAIRS;
    const float* dij   = (const float*)d_in[2];
    const float* rij   = (const float*)d_in[3];
    const float* emb   = (const float*)d_in[4];
    const float* e2w   = (const float*)d_in[5];
    const float* e2b   = (const float*)d_in[6];
    const float* dp1w  = (const float*)d_in[7];
    const float* dp1b  = (const float*)d_in[8];
    const float* dp2w  = (const float*)d_in[9];
    const float* dp2b  = (const float*)d_in[10];
    const float* dp3w  = (const float*)d_in[11];
    const float* dp3b  = (const float*)d_in[12];
    const float* lt0   = (const float*)d_in[13];
    const float* lt1   = (const float*)d_in[14];
    const float* lt2   = (const float*)d_in[15];
    const float* ls1w  = (const float*)d_in[16];
    const float* ls1b  = (const float*)d_in[17];
    const float* ls2w  = (const float*)d_in[18];
    const float* ls2b  = (const float*)d_in[19];
    const float* lng   = (const float*)d_in[20];
    const float* lnb   = (const float*)d_in[21];
    float* out = (float*)d_out;

    cudaFuncSetAttribute(k_prep, cudaFuncAttributeMaxDynamicSharedMemorySize, PREP_SMEM);
    cudaFuncSetAttribute(k_mlpfinal, cudaFuncAttributeMaxDynamicSharedMemorySize, MLPF_SMEM);

    k_pre<<<PRE_BLOCKS, 256>>>(psrc, emb, e2w, e2b, lt0, lt1, lt2, ls1w, ls2w);
    k_prep<<<(N_PAIRS + 255) / 256, 256, PREP_SMEM>>>(psrc, pdst, anum, dij, rij,
                                                      dp1w, dp2w, dp3w,
                                                      dp1b, dp2b, dp3b);
    k_pairs<<<N_ATOMS / 8, 256>>>(lng, lnb);
    k_mlpfinal<<<N_ATOMS / 8, 256, MLPF_SMEM>>>(ls1b, ls2b, out);
}

// round 10
// speedup vs baseline: 2.2893x; 1.0872x over previous
#include <cuda_runtime.h>
#include <math.h>

#define N_ATOMS 10000
#define N_PAIRS 100000
#define H 64
#define R 32
#define MAX_Z 100

typedef unsigned long long ull;

// -------- f32x2 packed math helpers (sm_10x) --------
__device__ __forceinline__ ull pk2(float x, float y) {
    ull r; asm("mov.b64 %0,{%1,%2};" : "=l"(r) : "f"(x), "f"(y)); return r;
}
__device__ __forceinline__ float2 up2(ull v) {
    float2 f; asm("mov.b64 {%0,%1},%2;" : "=f"(f.x), "=f"(f.y) : "l"(v)); return f;
}
__device__ __forceinline__ ull dup2(float x) { return pk2(x, x); }
__device__ __forceinline__ ull fma2_(ull a, ull b, ull c) {
    ull d; asm("fma.rn.f32x2 %0,%1,%2,%3;" : "=l"(d) : "l"(a), "l"(b), "l"(c)); return d;
}
__device__ __forceinline__ ull add2_(ull a, ull b) {
    ull d; asm("add.rn.f32x2 %0,%1,%2;" : "=l"(d) : "l"(a), "l"(b)); return d;
}
__device__ __forceinline__ ull mul2_(ull a, ull b) {
    ull d; asm("mul.rn.f32x2 %0,%1,%2;" : "=l"(d) : "l"(a), "l"(b)); return d;
}

// ---------------- scratch ----------------
__device__ __align__(16) float g_U[MAX_Z * H];
__device__ __align__(16) float g_V[MAX_Z * H];
__device__ __align__(16) float g_ltT[3 * H * H];    // [m][h][g]
__device__ __align__(16) float g_ls1T[64 * 128];    // [k][j]
__device__ __align__(16) float g_ls2T[128 * 192];   // [k][j]
__device__ int   g_counts[N_ATOMS];                 // zero-init; self-cleaned
__device__ int   g_offsets[N_ATOMS + 1];
__device__ int   g_cursor[N_ATOMS];
__device__ unsigned int g_ticket;                   // zero-init; self-cleaned
__device__ __align__(16) float4 g_geoA[N_PAIRS];    // ux,uy,uz,rc (slot-ordered)
__device__ __align__(16) float4 g_geoB[N_PAIRS];    // txx,tyy,tzz,-
__device__ __align__(16) float4 g_geoC[N_PAIRS];    // txy,txz,tyz,-
__device__ __align__(16) ull g_f1[N_PAIRS * 32];    // f1 per (pair, h-pair)
__device__ __align__(16) ull g_f2[N_PAIRS * 32];
__device__ __align__(16) ull g_f3[N_PAIRS * 32];
__device__ __align__(16) float g_comp[10][N_ATOMS * H];
__device__ __align__(16) float g_tnorm[N_ATOMS * H];

#define RBF_START 0.60653065971263342f
#define RBF_ALPHA 10.0f

#define HIST_BLOCKS 391
#define UV_BLOCKS   25
#define LTT_BLOCKS  48
#define L1T_BLOCKS  32
#define L2T_BLOCKS  96
#define PRE_BLOCKS  (HIST_BLOCKS + UV_BLOCKS + LTT_BLOCKS + L1T_BLOCKS + L2T_BLOCKS)

// ---------------- K_pre: hist + UV + transposes, then LAST BLOCK runs the scan --
__global__ void __launch_bounds__(256) k_pre(
    const int* __restrict__ src,
    const float* __restrict__ emb, const float* __restrict__ w2,
    const float* __restrict__ b2,
    const float* __restrict__ lt0, const float* __restrict__ lt1,
    const float* __restrict__ lt2,
    const float* __restrict__ ls1w, const float* __restrict__ ls2w) {
    int b = blockIdx.x;
    int tid = threadIdx.x;
    if (b < HIST_BLOCKS) {
        int i = b * 256 + tid;
        if (i < N_PAIRS) atomicAdd(&g_counts[src[i]], 1);
    } else if (b < HIST_BLOCKS + UV_BLOCKS) {
        __shared__ float se[4][H];
        int ty = tid >> 6;
        int h  = tid & 63;
        int t  = (b - HIST_BLOCKS) * 4 + ty;
        se[ty][h] = emb[t * H + h];
        __syncthreads();
        float u = b2[h];
        float v = 0.0f;
        const float* wr = w2 + h * 2 * H;
#pragma unroll
        for (int k = 0; k < H; k++) {
            u += se[ty][k] * wr[k];
            v += se[ty][k] * wr[H + k];
        }
        g_U[t * H + h] = u;
        g_V[t * H + h] = v;
    } else if (b < HIST_BLOCKS + UV_BLOCKS + LTT_BLOCKS) {
        int idx = (b - HIST_BLOCKS - UV_BLOCKS) * 256 + tid;   // < 12288
        int m = idx >> 12;
        int rem = idx & 4095;
        int g = rem >> 6, h = rem & 63;
        const float* s = (m == 0) ? lt0 : (m == 1) ? lt1 : lt2;
        g_ltT[m * 4096 + h * 64 + g] = s[rem];
    } else if (b < HIST_BLOCKS + UV_BLOCKS + LTT_BLOCKS + L1T_BLOCKS) {
        int idx = (b - HIST_BLOCKS - UV_BLOCKS - LTT_BLOCKS) * 256 + tid;  // < 8192
        int k = idx >> 7, j = idx & 127;
        g_ls1T[idx] = ls1w[j * 64 + k];
    } else {
        int idx = (b - HIST_BLOCKS - UV_BLOCKS - LTT_BLOCKS - L1T_BLOCKS) * 256 + tid;
        int k = idx / 192, j = idx - k * 192;   // idx < 24576
        g_ls2T[idx] = ls2w[j * 128 + k];
    }

    // ---- last-block ticket: the final block to finish runs the scan ----
    __shared__ int s_last;
    __syncthreads();
    if (tid == 0) {
        __threadfence();
        unsigned int t = atomicAdd(&g_ticket, 1u);
        s_last = (t == (unsigned)(PRE_BLOCKS - 1)) ? 1 : 0;
    }
    __syncthreads();
    if (!s_last) return;
    __threadfence();   // acquire all producers' writes

    // scan of g_counts[0..9999] with 256 threads, 40 elems/thread (guarded)
    __shared__ int wsum[8];
    {
        int lane = tid & 31, wid = tid >> 5;
        int base = tid * 40;
        int loc[40];
        int s = 0;
#pragma unroll
        for (int i = 0; i < 40; i++) {
            int idx = base + i;
            int c = (idx < N_ATOMS) ? g_counts[idx] : 0;
            loc[i] = s;
            s += c;
        }
        int v = s;
#pragma unroll
        for (int o = 1; o < 32; o <<= 1) {
            int u = __shfl_up_sync(0xffffffffu, v, o);
            if (lane >= o) v += u;
        }
        if (lane == 31) wsum[wid] = v;
        __syncthreads();
        if (wid == 0 && lane < 8) {
            int x = wsum[lane];
#pragma unroll
            for (int o = 1; o < 8; o <<= 1) {
                int u = __shfl_up_sync(0xffu, x, o);
                if (lane >= o) x += u;
            }
            wsum[lane] = x;
        }
        __syncthreads();
        int wbase = (wid > 0) ? wsum[wid - 1] : 0;
        int excl = wbase + v - s;
#pragma unroll
        for (int i = 0; i < 40; i++) {
            int idx = base + i;
            if (idx < N_ATOMS) {
                int o = excl + loc[i];
                g_offsets[idx] = o;
                g_cursor[idx]  = o;
                g_counts[idx]  = 0;   // restore invariant for next replay
            }
        }
        if (tid == 255) {
            g_offsets[N_ATOMS] = wbase + v;
            g_ticket = 0;             // restore invariant for next replay
        }
    }
}

// ---------------- K_prep: scatter + geometry + rbf + f1/f2/f3 GEMM ----------
#define PREP_SMEM (16384 + 8192 + 32768)
__global__ void __launch_bounds__(256) k_prep(
    const int* __restrict__ src, const int* __restrict__ pdst,
    const int* __restrict__ anum,
    const float* __restrict__ dij, const float* __restrict__ rij,
    const float* __restrict__ dp1w, const float* __restrict__ dp2w,
    const float* __restrict__ dp3w,
    const float* __restrict__ dp1b, const float* __restrict__ dp2b,
    const float* __restrict__ dp3b) {
    extern __shared__ char smraw[];
    ulonglong2* sh_dp12 = reinterpret_cast<ulonglong2*>(smraw);          // [r*32+lane]
    ull*        sh_dp3  = reinterpret_cast<ull*>(smraw + 16384);
    float*      s_rbf   = reinterpret_cast<float*>(smraw + 24576);      // [w][p][r]

    int tid = threadIdx.x;
    for (int e = tid; e < R * 32; e += 256) {
        int r = e >> 5, l = e & 31;
        int h0 = 2 * l, h1 = h0 + 1;
        sh_dp12[e] = make_ulonglong2(pk2(dp1w[h0 * R + r], dp1w[h1 * R + r]),
                                     pk2(dp2w[h0 * R + r], dp2w[h1 * R + r]));
        sh_dp3[e]  = pk2(dp3w[h0 * R + r], dp3w[h1 * R + r]);
    }
    __syncthreads();

    int w = tid >> 5, lane = tid & 31;
    int i = blockIdx.x * 256 + tid;
    if ((i & ~31) >= N_PAIRS) return;     // whole warps only (N_PAIRS % 32 == 0)

    // stage 1: geometry + scatter
    float d = dij[i];
    float rc = (d < 0.5f) ? 0.5f * (__cosf(6.2831853071795865f * d) + 1.0f) : 0.0f;
    int za = anum[src[i]];
    int zd = anum[pdst[i]];
    float rx = rij[3 * i], ry = rij[3 * i + 1], rz = rij[3 * i + 2];
    float inv = 1.0f / d;
    float ux = rx * inv, uy = ry * inv, uz = rz * inv;
    float tr3 = (ux * ux + uy * uy + uz * uz) * (1.0f / 3.0f);
    float ee = __expf(-RBF_ALPHA * d);
    int pos = atomicAdd(&g_cursor[src[i]], 1);
    g_geoA[pos] = make_float4(ux, uy, uz, rc);
    g_geoB[pos] = make_float4(ux * ux - tr3, uy * uy - tr3, uz * uz - tr3, 0.0f);
    g_geoC[pos] = make_float4(ux * uy, ux * uz, uy * uz, 0.0f);

    // stage 2: warp-cooperative rbf -> smem [p][r]
    const float rbf_step = (1.0f - RBF_START) * (1.0f / 31.0f);
    float tb = (1.0f - RBF_START) * (2.0f / 32.0f);
    const float beta = 1.0f / (tb * tb);
    const float mlane = RBF_START + rbf_step * (float)lane;
    float* myrbf = s_rbf + w * 1024;
#pragma unroll 4
    for (int j = 0; j < 32; j++) {
        float ee_b = __shfl_sync(0xffffffffu, ee, j);
        float rc_b = __shfl_sync(0xffffffffu, rc, j);
        float dfm = ee_b - mlane;
        myrbf[j * 32 + lane] = __expf(-beta * dfm * dfm) * rc_b;
    }
    __syncwarp();

    float2 b1v = reinterpret_cast<const float2*>(dp1b)[lane];
    float2 b2v = reinterpret_cast<const float2*>(dp2b)[lane];
    float2 b3v = reinterpret_cast<const float2*>(dp3b)[lane];
    ull b1p = pk2(b1v.x, b1v.y);
    ull b2p = pk2(b2v.x, b2v.y);
    ull b3p = pk2(b3v.x, b3v.y);
    const ull tenp = dup2(10.0f);
    const ull hunp = dup2(100.0f);
    const float2* U2 = reinterpret_cast<const float2*>(g_U);
    const float2* V2 = reinterpret_cast<const float2*>(g_V);

    // stage 3: rbf @ W, fold C, write f1/f2/f3
#pragma unroll 1
    for (int grp = 0; grp < 4; grp++) {
        ull g1[8] = {0,0,0,0,0,0,0,0};
        ull g2[8] = {0,0,0,0,0,0,0,0};
        ull g3[8] = {0,0,0,0,0,0,0,0};
        const float* rb = myrbf + grp * 8 * 32;
#pragma unroll
        for (int r = 0; r < R; r++) {
            ulonglong2 w12 = sh_dp12[r * 32 + lane];
            ull w3 = sh_dp3[r * 32 + lane];
#pragma unroll
            for (int pi = 0; pi < 8; pi++) {
                ull rv = dup2(rb[pi * 32 + r]);
                g1[pi] = fma2_(rv, w12.x, g1[pi]);
                g2[pi] = fma2_(rv, w12.y, g2[pi]);
                g3[pi] = fma2_(rv, w3,    g3[pi]);
            }
        }
#pragma unroll
        for (int pi = 0; pi < 8; pi++) {
            int p = grp * 8 + pi;
            int   pos_b = __shfl_sync(0xffffffffu, pos, p);
            int   za_b  = __shfl_sync(0xffffffffu, za,  p);
            int   zd_b  = __shfl_sync(0xffffffffu, zd,  p);
            float rc_b  = __shfl_sync(0xffffffffu, rc,  p);
            float2 ubv = U2[za_b * 32 + lane];
            float2 vbv = V2[zd_b * 32 + lane];
            ull Cp = pk2(rc_b * (ubv.x + vbv.x), rc_b * (ubv.y + vbv.y));
            g_f1[pos_b * 32 + lane] = mul2_(add2_(g1[pi], b1p), Cp);
            g_f2[pos_b * 32 + lane] = mul2_(mul2_(add2_(g2[pi], b2p), Cp), tenp);
            g_f3[pos_b * 32 + lane] = mul2_(mul2_(add2_(g3[pi], b3p), Cp), hunp);
        }
    }
}

// ---------------- K_pairs: pure streaming accumulate + layernorm ----------------
__global__ void __launch_bounds__(256) k_pairs(
    const float* __restrict__ lng, const float* __restrict__ lnb) {
    int w    = threadIdx.x >> 5;
    int lane = threadIdx.x & 31;
    int a    = blockIdx.x * 8 + w;

    int start = g_offsets[a];
    int end   = g_offsets[a + 1];

    ull cI = 0, wx = 0, wy = 0, wz = 0;
    ull sxx = 0, syy = 0, szz = 0, sxy = 0, sxz = 0, syz = 0;

#pragma unroll 2
    for (int idx = start; idx < end; idx++) {
        ull f1 = g_f1[idx * 32 + lane];
        ull f2 = g_f2[idx * 32 + lane];
        ull f3 = g_f3[idx * 32 + lane];
        float4 gA = g_geoA[idx];
        float4 gB = g_geoB[idx];
        float4 gC = g_geoC[idx];
        cI  = add2_(cI, f1);
        wx  = fma2_(f2, dup2(gA.x), wx);
        wy  = fma2_(f2, dup2(gA.y), wy);
        wz  = fma2_(f2, dup2(gA.z), wz);
        sxx = fma2_(f3, dup2(gB.x), sxx);
        syy = fma2_(f3, dup2(gB.y), syy);
        szz = fma2_(f3, dup2(gB.z), szz);
        sxy = fma2_(f3, dup2(gC.x), sxy);
        sxz = fma2_(f3, dup2(gC.y), sxz);
        syz = fma2_(f3, dup2(gC.z), syz);
    }

    float2 cIf = up2(cI),  wxf = up2(wx),  wyf = up2(wy),  wzf = up2(wz);
    float2 sxxf = up2(sxx), syyf = up2(syy), szzf = up2(szz);
    float2 sxyf = up2(sxy), sxzf = up2(sxz), syzf = up2(syz);

    float tA0 = cIf.x + sxxf.x, tB0 = cIf.x + syyf.x, tC0 = cIf.x + szzf.x;
    float tn0 = tA0*tA0 + tB0*tB0 + tC0*tC0
              + 2.0f * (sxyf.x*sxyf.x + wzf.x*wzf.x + sxzf.x*sxzf.x
                      + wyf.x*wyf.x + syzf.x*syzf.x + wxf.x*wxf.x);
    float tA1 = cIf.y + sxxf.y, tB1 = cIf.y + syyf.y, tC1 = cIf.y + szzf.y;
    float tn1 = tA1*tA1 + tB1*tB1 + tC1*tC1
              + 2.0f * (sxyf.y*sxyf.y + wzf.y*wzf.y + sxzf.y*sxzf.y
                      + wyf.y*wyf.y + syzf.y*syzf.y + wxf.y*wxf.y);

    float ssum = tn0 + tn1;
#pragma unroll
    for (int o = 16; o; o >>= 1) ssum += __shfl_xor_sync(0xffffffffu, ssum, o);
    float mu = ssum * (1.0f / 64.0f);
    float e0 = tn0 - mu, e1 = tn1 - mu;
    float vsum = e0 * e0 + e1 * e1;
#pragma unroll
    for (int o = 16; o; o >>= 1) vsum += __shfl_xor_sync(0xffffffffu, vsum, o);
    float rstd = rsqrtf(vsum * (1.0f / 64.0f) + 1e-5f);

    float2 lg = reinterpret_cast<const float2*>(lng)[lane];
    float2 lb = reinterpret_cast<const float2*>(lnb)[lane];
    float2 nrm;
    nrm.x = e0 * rstd * lg.x + lb.x;
    nrm.y = e1 * rstd * lg.y + lb.y;
    reinterpret_cast<float2*>(g_tnorm)[a * 32 + lane] = nrm;

    int oidx = a * 32 + lane;
    reinterpret_cast<float2*>(g_comp[0])[oidx] = cIf;
    reinterpret_cast<float2*>(g_comp[1])[oidx] = wxf;
    reinterpret_cast<float2*>(g_comp[2])[oidx] = wyf;
    reinterpret_cast<float2*>(g_comp[3])[oidx] = wzf;
    reinterpret_cast<float2*>(g_comp[4])[oidx] = sxxf;
    reinterpret_cast<float2*>(g_comp[5])[oidx] = syyf;
    reinterpret_cast<float2*>(g_comp[6])[oidx] = szzf;
    reinterpret_cast<float2*>(g_comp[7])[oidx] = sxyf;
    reinterpret_cast<float2*>(g_comp[8])[oidx] = sxzf;
    reinterpret_cast<float2*>(g_comp[9])[oidx] = syzf;
}

// ---------------- K_mlpfinal: 16 atoms/block, bank-exact layouts ----------
// smem (ull): region[5760] (csh [c][h][q]=c*512+h*8+q then res [c][g][q9]=c*576+g*9+q)
//             nshT[512] ([k][q]=k*8+q), h1T[1024] ([hq][j][i]=hq*256+j*2+i),
//             nm float[3072] = 1536 ull ([atom][j2])
#define MLPF_ULL (5760 + 512 + 1024 + 1536)
#define MLPF_SMEM (MLPF_ULL * 8)
__global__ void __launch_bounds__(640) k_mlpfinal(
    const float* __restrict__ ls1b, const float* __restrict__ ls2b,
    float* __restrict__ out) {
    extern __shared__ __align__(16) ull smu[];
    ull*   region = smu;
    ull*   nshT   = smu + 5760;
    ull*   h1T    = smu + 6272;
    float* nm     = reinterpret_cast<float*>(smu + 7296);   // 3072 floats
    float* resf   = reinterpret_cast<float*>(region);

    int tid = threadIdx.x;
    int ab  = blockIdx.x * 16;

    // ---- stage csh [c][h][q]: unit=(c,h,q4) packs 4 atoms -> 2 ull (STS.128)
#pragma unroll
    for (int it = 0; it < 4; it++) {
        int u = it * 640 + tid;          // < 2560
        int q4 = u & 3;
        int h  = (u >> 2) & 63;
        int c  = u >> 8;                 // 0..9
        const float* cp = g_comp[c] + (ab + 4 * q4) * 64 + h;
        float v0 = cp[0], v1 = cp[64], v2 = cp[128], v3 = cp[192];
        *reinterpret_cast<ulonglong2*>(region + c * 512 + h * 8 + 2 * q4) =
            make_ulonglong2(pk2(v0, v1), pk2(v2, v3));
    }
    // ---- stage nshT [k][q]
    if (tid < 256) {
        int q4 = tid & 3;
        int k  = tid >> 2;
        const float* tp = g_tnorm + (ab + 4 * q4) * 64 + k;
        float v0 = tp[0], v1 = tp[64], v2 = tp[128], v3 = tp[192];
        *reinterpret_cast<ulonglong2*>(nshT + k * 8 + 2 * q4) =
            make_ulonglong2(pk2(v0, v1), pk2(v2, v3));
    }
    __syncthreads();

    // ---- channel-mix GEMM: thread=(c,g), 16 atoms register-blocked
    ull acc[8];
    int c = tid >> 6, g = tid & 63;
    {
        int m = (c == 0) ? 0 : (c < 4) ? 1 : 2;
        const float* wcol = g_ltT + m * 4096 + g;
#pragma unroll
        for (int i = 0; i < 8; i++) acc[i] = 0ull;
#pragma unroll 4
        for (int h = 0; h < 64; h++) {
            ull wd = dup2(wcol[h * 64]);                      // coalesced LDG, L1-hit
            const ulonglong2* q = reinterpret_cast<const ulonglong2*>(region + c * 512 + h * 8);
            ulonglong2 q0 = q[0], q1 = q[1], q2 = q[2], q3 = q[3];   // broadcast LDS.128
            acc[0] = fma2_(wd, q0.x, acc[0]);
            acc[1] = fma2_(wd, q0.y, acc[1]);
            acc[2] = fma2_(wd, q1.x, acc[2]);
            acc[3] = fma2_(wd, q1.y, acc[3]);
            acc[4] = fma2_(wd, q2.x, acc[4]);
            acc[5] = fma2_(wd, q2.y, acc[5]);
            acc[6] = fma2_(wd, q3.x, acc[6]);
            acc[7] = fma2_(wd, q3.y, acc[7]);
        }
    }
    __syncthreads();   // all csh reads done; region is reusable

    // ---- write res [c][g][q-pad9] (STS.64, low conflict) + MLP layer 1
    {
        ull* rp = region + c * 576 + g * 9;
#pragma unroll
        for (int i = 0; i < 8; i++) rp[i] = acc[i];
    }
    if (tid < 512) {
        int j = tid & 127, hq = tid >> 7;       // hq 0..3 -> atoms 4hq..4hq+3
        ull bp = dup2(ls1b[j]);
        ull a0 = bp, a1 = bp;
        const float* wcol = g_ls1T + j;
#pragma unroll 8
        for (int k = 0; k < 64; k++) {
            ull wd = dup2(wcol[k * 128]);
            ulonglong2 hv = *reinterpret_cast<const ulonglong2*>(nshT + k * 8 + 2 * hq);
            a0 = fma2_(wd, hv.x, a0);
            a1 = fma2_(wd, hv.y, a1);
        }
        float2 f0 = up2(a0), f1v = up2(a1);
        float r0 = f0.x  / (1.0f + __expf(-f0.x));
        float r1 = f0.y  / (1.0f + __expf(-f0.y));
        float r2 = f1v.x / (1.0f + __expf(-f1v.x));
        float r3 = f1v.y / (1.0f + __expf(-f1v.y));
        *reinterpret_cast<ulonglong2*>(h1T + hq * 256 + j * 2) =
            make_ulonglong2(pk2(r0, r1), pk2(r2, r3));      // coalesced STS.128
    }
    __syncthreads();

    // ---- MLP layer 2: 128 -> 192, silu; thread=(j2, grp of 8 atoms)
    if (tid < 384) {
        int j2 = tid % 192, grp = tid / 192;
        ull bp = dup2(ls2b[j2]);
        ull acc2[4] = {bp, bp, bp, bp};
        const float* wcol = g_ls2T + j2;
        const ull* hA = h1T + (2 * grp) * 256;
        const ull* hB = h1T + (2 * grp + 1) * 256;
#pragma unroll 4
        for (int k = 0; k < 128; k++) {
            ull wd = dup2(wcol[k * 192]);
            ulonglong2 A = *reinterpret_cast<const ulonglong2*>(hA + k * 2);
            ulonglong2 B = *reinterpret_cast<const ulonglong2*>(hB + k * 2);
            acc2[0] = fma2_(wd, A.x, acc2[0]);
            acc2[1] = fma2_(wd, A.y, acc2[1]);
            acc2[2] = fma2_(wd, B.x, acc2[2]);
            acc2[3] = fma2_(wd, B.y, acc2[3]);
        }
#pragma unroll
        for (int i2 = 0; i2 < 4; i2++) {
            float2 f = up2(acc2[i2]);
            nm[(8 * grp + 2 * i2)     * 192 + j2] = f.x / (1.0f + __expf(-f.x));
            nm[(8 * grp + 2 * i2 + 1) * 192 + j2] = f.y / (1.0f + __expf(-f.y));
        }
    }
    __syncthreads();

    // ---- assemble 3x3 outputs (coalesced stores)
#pragma unroll
    for (int e = tid; e < 9216; e += 640) {
        int aa = e / 576;
        int rem = e - aa * 576;
        int g2 = rem / 9;
        int ij = rem - g2 * 9;
        int i3 = (ij * 11) >> 5;
        int jc = ij - i3 * 3;
        bool dg = (i3 == jc);
        int sidx = dg ? (4 + i3) : (6 + i3 + jc);
        int aidx = dg ? 1 : (4 - (i3 + jc));
        float sgn = dg ? 0.0f : ((((i3 - jc) + 3) % 3 == 1) ? 1.0f : -1.0f);
        float n0 = nm[aa * 192 + g2 * 3 + 0];
        float n1 = nm[aa * 192 + g2 * 3 + 1];
        float n2 = nm[aa * 192 + g2 * 3 + 2];
        float cIv = resf[g2 * 18 + aa];
        float av  = resf[aidx * 1152 + g2 * 18 + aa];
        float sv  = resf[sidx * 1152 + g2 * 18 + aa];
        float iv = dg ? cIv : 0.0f;
        out[ab * 576 + e] = iv * n0 + sgn * av * n1 + sv * n2;
    }
}

// ---------------- launch ----------------
extern "C" void kernel_launch(void* const* d_in, const int* in_sizes, int n_in,
                              void* d_out, int out_size) {
    const int*   anum  = (const int*)d_in[0];
    const int*   psrc  = (const int*)d_in[1];
    const int*   pdst  = psrc + N_PAIRS;
    const float* dij   = (const float*)d_in[2];
    const float* rij   = (const float*)d_in[3];
    const float* emb   = (const float*)d_in[4];
    const float* e2w   = (const float*)d_in[5];
    const float* e2b   = (const float*)d_in[6];
    const float* dp1w  = (const float*)d_in[7];
    const float* dp1b  = (const float*)d_in[8];
    const float* dp2w  = (const float*)d_in[9];
    const float* dp2b  = (const float*)d_in[10];
    const float* dp3w  = (const float*)d_in[11];
    const float* dp3b  = (const float*)d_in[12];
    const float* lt0   = (const float*)d_in[13];
    const float* lt1   = (const float*)d_in[14];
    const float* lt2   = (const float*)d_in[15];
    const float* ls1w  = (const float*)d_in[16];
    const float* ls1b  = (const float*)d_in[17];
    const float* ls2w  = (const float*)d_in[18];
    const float* ls2b  = (const float*)d_in[19];
    const float* lng   = (const float*)d_in[20];
    const float* lnb   = (const float*)d_in[21];
    float* out = (float*)d_out;

    cudaFuncSetAttribute(k_prep, cudaFuncAttributeMaxDynamicSharedMemorySize, PREP_SMEM);
    cudaFuncSetAttribute(k_mlpfinal, cudaFuncAttributeMaxDynamicSharedMemorySize, MLPF_SMEM);

    k_pre<<<PRE_BLOCKS, 256>>>(psrc, emb, e2w, e2b, lt0, lt1, lt2, ls1w, ls2w);
    k_prep<<<(N_PAIRS + 255) / 256, 256, PREP_SMEM>>>(psrc, pdst, anum, dij, rij,
                                                      dp1w, dp2w, dp3w,
                                                      dp1b, dp2b, dp3b);
    k_pairs<<<N_ATOMS / 8, 256>>>(lng, lnb);
    k_mlpfinal<<<N_ATOMS / 16, 640, MLPF_SMEM>>>(ls1b, ls2b, out);
}